// round 6
// baseline (speedup 1.0000x reference)
#include <cuda_runtime.h>
#include <math.h>
#include <stdint.h>

// ---------------- problem constants ----------------
#define PN   2048
#define PD   1024
#define PH   16
#define PKV  4
#define PDH  64
#define PE   8
#define PF   2048
#define PCH  64
#define P_EPS 1e-6f
#define P_DT  0.1f
#define P_BASE_SCALE 10.0f

// ---------------- scratch ----------------
__device__ float g_hnorm[PN * PD];
__device__ float g_q[PN * PH * PDH];
__device__ float g_k[PN * PKV * PDH];
__device__ float g_v[PN * PKV * PDH];
__device__ float g_attno[PN * PD];
__device__ float g_o[PN * PD];
__device__ float g_ctrl[PN * PCH];
__device__ float g_co[PN * 3 * PD];
__device__ float g_hidmid[PN * PD];
__device__ float g_xnorm[PN * PD];
__device__ float g_G[PN * PF];
__device__ float g_U[PN * PF];
__device__ float g_mid[PN * PF];
__device__ float g_cosT[PN * 32];
__device__ float g_sinT[PN * 32];
__device__ int   g_elist[PE * PN];
__device__ int   g_ecount[PE];

// ---------------- helpers ----------------
__device__ __forceinline__ float sigmoidf_(float x) { return 1.0f / (1.0f + expf(-x)); }
__device__ __forceinline__ float softplusf_(float x) {
    return fmaxf(x, 0.0f) + log1pf(expf(-fabsf(x)));
}
__device__ __forceinline__ uint32_t f2tf32(float f) {
    uint32_t r; asm("cvt.rna.tf32.f32 %0, %1;" : "=r"(r) : "f"(f)); return r;
}
__device__ __forceinline__ void mma_tf32(float* d, const uint32_t* a, const uint32_t* b) {
    asm volatile(
        "mma.sync.aligned.m16n8k8.row.col.f32.tf32.tf32.f32 "
        "{%0,%1,%2,%3}, {%4,%5,%6,%7}, {%8,%9}, {%0,%1,%2,%3};"
        : "+f"(d[0]), "+f"(d[1]), "+f"(d[2]), "+f"(d[3])
        : "r"(a[0]), "r"(a[1]), "r"(a[2]), "r"(a[3]), "r"(b[0]), "r"(b[1]));
}

__global__ void zero_counts_kernel() {
    int t = threadIdx.x;
    if (t < PE) g_ecount[t] = 0;
}

__global__ void rope_table_kernel(const int* __restrict__ positions) {
    __shared__ float sm_inv[32];
    if (threadIdx.x < 32) {
        double inv = pow(10000.0, -((double)(2 * threadIdx.x)) / 64.0);
        sm_inv[threadIdx.x] = (float)inv;
    }
    __syncthreads();
    int i = blockIdx.x * 256 + threadIdx.x;
    if (i >= PN * 32) return;
    int n = i >> 5, f = i & 31;
    float ang = (float)positions[n] * sm_inv[f];
    float s, c;
    sincosf(ang, &s, &c);
    g_cosT[i] = c;
    g_sinT[i] = s;
}

__global__ void rmsnorm_kernel(const float* __restrict__ x, const float* __restrict__ w,
                               float* __restrict__ out) {
    int row = blockIdx.x;
    int tid = threadIdx.x;
    __shared__ float red[256];
    const float* xr = x + (size_t)row * PD;
    float s = 0.0f;
    for (int d = tid; d < PD; d += 256) { float v = xr[d]; s += v * v; }
    red[tid] = s; __syncthreads();
    for (int off = 128; off > 0; off >>= 1) {
        if (tid < off) red[tid] += red[tid + off];
        __syncthreads();
    }
    float scale = rsqrtf(red[0] / (float)PD + P_EPS);
    float* orow = out + (size_t)row * PD;
    for (int d = tid; d < PD; d += 256) orow[d] = xr[d] * scale * w[d];
}

// ======================================================================
// Shared GEMM tile machinery (pair-packed smem, LDS.64 fragments)
//   As[128][24]: k-pair (kk, kk+4) adjacent; row stride 24 words (conflict-free LDS.64)
//   Bs[8][264] : pair p = s*4+lc holds rows {s*8+lc, s*8+lc+4}; stride 264 (mod32=8)
// ======================================================================
#define ASTRIDE 24
#define BSTRIDE 264

struct GDesc {
    const float* A; const float* A2;
    const float* B; const float* B2;
    const float* bias;
    float* C;
    int Nc; int K; int K1; int flags;    // flags bit1: SiLU
};

__global__ __launch_bounds__(256, 2)
void tf32_gemm_multi(GDesc d0, GDesc d1, GDesc d2) {
    __shared__ uint32_t As[2][128][ASTRIDE];
    __shared__ uint32_t Bs[2][8][BSTRIDE];

    GDesc d = (blockIdx.z == 0) ? d0 : ((blockIdx.z == 1) ? d1 : d2);
    int m0 = blockIdx.y * 128;
    int n0 = blockIdx.x * 128;
    if (n0 >= d.Nc) return;

    int tid  = threadIdx.x;
    int lane = tid & 31;
    int w    = tid >> 5;
    int wm   = w >> 1;
    int wn   = w & 1;
    int lr   = lane >> 2, lc = lane & 3;

    int a_r  = tid >> 2;
    int a_kq = (tid & 3) * 4;
    int b_k  = tid >> 5;                       // 0..7
    int k_a  = (b_k & 3) + ((b_k >> 2) << 3);  // {0..3, 8..11}
    int b_pair = (b_k & 3) + ((b_k >> 2) << 2);// 0..7
    int b_nq = (tid & 31) * 4;

    float4 aV[2], bV[2];
    float acc[2][8][4];
#pragma unroll
    for (int mf = 0; mf < 2; mf++)
#pragma unroll
        for (int nf = 0; nf < 8; nf++)
#pragma unroll
            for (int c = 0; c < 4; c++) acc[mf][nf][c] = 0.0f;

    auto loadA = [&](int k0) {
        const float* Ap = d.A; int lda = d.K1; int kk = k0;
        if (k0 >= d.K1) { Ap = d.A2; lda = d.K - d.K1; kk = k0 - d.K1; }
#pragma unroll
        for (int i = 0; i < 2; i++) {
            int pos = m0 + a_r + i * 64;
            aV[i] = *reinterpret_cast<const float4*>(&Ap[(size_t)pos * lda + kk + a_kq]);
        }
    };
    auto loadB = [&](int k0) {
        const float* Bp = d.B; int kk = k0;
        if (k0 >= d.K1) { Bp = d.B2; kk = k0 - d.K1; }
        int col = n0 + b_nq;
#pragma unroll
        for (int i = 0; i < 2; i++) {
            if (col < d.Nc) {
                bV[i] = *reinterpret_cast<const float4*>(&Bp[(size_t)(kk + k_a + i * 4) * d.Nc + col]);
            } else {
                bV[i] = make_float4(0.f, 0.f, 0.f, 0.f);
            }
        }
    };
    auto stsTile = [&](int buf) {
        // A: k index a_kq+j -> pair position
#pragma unroll
        for (int i = 0; i < 2; i++) {
            int r = a_r + i * 64;
            float av[4] = { aV[i].x, aV[i].y, aV[i].z, aV[i].w };
#pragma unroll
            for (int j = 0; j < 4; j++) {
                int k = a_kq + j;
                int s = k >> 3, ww = k & 7;
                int pos = ((s << 2) + (ww & 3)) * 2 + (ww >> 2);
                As[buf][r][pos] = f2tf32(av[j]);
            }
        }
        // B: interleave rows (k_a, k_a+4) -> 2x STS.128
        uint32_t* dst = &Bs[buf][b_pair][b_nq * 2];
        uint4 p0 = make_uint4(f2tf32(bV[0].x), f2tf32(bV[1].x),
                              f2tf32(bV[0].y), f2tf32(bV[1].y));
        uint4 p1 = make_uint4(f2tf32(bV[0].z), f2tf32(bV[1].z),
                              f2tf32(bV[0].w), f2tf32(bV[1].w));
        *reinterpret_cast<uint4*>(dst)     = p0;
        *reinterpret_cast<uint4*>(dst + 4) = p1;
    };

    loadA(0); loadB(0);
    stsTile(0);
    __syncthreads();

    int buf = 0;
    for (int k0 = 16; k0 <= d.K; k0 += 16) {
        bool nxt = (k0 < d.K);
        if (nxt) { loadA(k0); loadB(k0); }
#pragma unroll
        for (int s = 0; s < 2; s++) {
            uint32_t afr[2][4], bfr[8][2];
            int pidx = (s << 2) + lc;
#pragma unroll
            for (int mf = 0; mf < 2; mf++) {
                int rb = wm * 32 + mf * 16 + lr;
                uint2 a01 = *reinterpret_cast<const uint2*>(&As[buf][rb][pidx * 2]);
                uint2 a23 = *reinterpret_cast<const uint2*>(&As[buf][rb + 8][pidx * 2]);
                afr[mf][0] = a01.x; afr[mf][1] = a23.x;
                afr[mf][2] = a01.y; afr[mf][3] = a23.y;
            }
#pragma unroll
            for (int nf = 0; nf < 8; nf++) {
                int cb = wn * 64 + nf * 8 + lr;
                uint2 b01 = *reinterpret_cast<const uint2*>(&Bs[buf][pidx][cb * 2]);
                bfr[nf][0] = b01.x; bfr[nf][1] = b01.y;
            }
#pragma unroll
            for (int mf = 0; mf < 2; mf++)
#pragma unroll
                for (int nf = 0; nf < 8; nf++)
                    mma_tf32(acc[mf][nf], afr[mf], bfr[nf]);
        }
        if (nxt) stsTile(buf ^ 1);
        __syncthreads();
        buf ^= 1;
    }

#pragma unroll
    for (int mf = 0; mf < 2; mf++) {
#pragma unroll
        for (int r2 = 0; r2 < 2; r2++) {
            int crow = m0 + wm * 32 + mf * 16 + lr + r2 * 8;
#pragma unroll
            for (int nf = 0; nf < 8; nf++) {
#pragma unroll
                for (int c2 = 0; c2 < 2; c2++) {
                    int col = n0 + wn * 64 + nf * 8 + lc * 2 + c2;
                    if (col >= d.Nc) continue;
                    size_t ci = (size_t)crow * d.Nc + col;
                    float val = acc[mf][nf][r2 * 2 + c2];
                    if (d.bias) val += d.bias[col];
                    if (d.flags & 2) val = val / (1.0f + expf(-val));
                    d.C[ci] = val;
                }
            }
        }
    }
}

// ---------------- MoE GEMM: grid.z = expert, gate/up split along x ----------------
__global__ __launch_bounds__(256, 2)
void moe_gemm_kernel(const float* __restrict__ A,
                     const float* __restrict__ Bg, const float* __restrict__ Bu,
                     size_t bStride, float* __restrict__ Cg, float* __restrict__ Cu,
                     const float* __restrict__ residual,
                     int Nc, int K, int xPart) {
    __shared__ uint32_t As[2][128][ASTRIDE];
    __shared__ uint32_t Bs[2][8][BSTRIDE];

    int e = blockIdx.z;
    int cnt = g_ecount[e];
    int m0 = blockIdx.y * 128;
    if (m0 >= cnt) return;
    int part = blockIdx.x / xPart;
    int n0 = (blockIdx.x % xPart) * 128;
    const float* B = (part ? Bu : Bg) + (size_t)e * bStride;
    float* C = part ? Cu : Cg;
    const int* gather = g_elist + e * PN;

    int tid  = threadIdx.x;
    int lane = tid & 31;
    int w    = tid >> 5;
    int wm   = w >> 1;
    int wn   = w & 1;
    int lr   = lane >> 2, lc = lane & 3;

    int a_r  = tid >> 2;
    int a_kq = (tid & 3) * 4;
    int b_k  = tid >> 5;
    int k_a  = (b_k & 3) + ((b_k >> 2) << 3);
    int b_pair = (b_k & 3) + ((b_k >> 2) << 2);
    int b_nq = (tid & 31) * 4;

    float4 aV[2], bV[2];
    float acc[2][8][4];
#pragma unroll
    for (int mf = 0; mf < 2; mf++)
#pragma unroll
        for (int nf = 0; nf < 8; nf++)
#pragma unroll
            for (int c = 0; c < 4; c++) acc[mf][nf][c] = 0.0f;

    auto loadA = [&](int k0) {
#pragma unroll
        for (int i = 0; i < 2; i++) {
            int pos = m0 + a_r + i * 64;
            if (pos < cnt) {
                int ar = gather[pos];
                aV[i] = *reinterpret_cast<const float4*>(&A[(size_t)ar * K + k0 + a_kq]);
            } else {
                aV[i] = make_float4(0.f, 0.f, 0.f, 0.f);
            }
        }
    };
    auto loadB = [&](int k0) {
        int col = n0 + b_nq;
#pragma unroll
        for (int i = 0; i < 2; i++)
            bV[i] = *reinterpret_cast<const float4*>(&B[(size_t)(k0 + k_a + i * 4) * Nc + col]);
    };
    auto stsTile = [&](int buf) {
#pragma unroll
        for (int i = 0; i < 2; i++) {
            int r = a_r + i * 64;
            float av[4] = { aV[i].x, aV[i].y, aV[i].z, aV[i].w };
#pragma unroll
            for (int j = 0; j < 4; j++) {
                int k = a_kq + j;
                int s = k >> 3, ww = k & 7;
                int pos = ((s << 2) + (ww & 3)) * 2 + (ww >> 2);
                As[buf][r][pos] = f2tf32(av[j]);
            }
        }
        uint32_t* dst = &Bs[buf][b_pair][b_nq * 2];
        uint4 p0 = make_uint4(f2tf32(bV[0].x), f2tf32(bV[1].x),
                              f2tf32(bV[0].y), f2tf32(bV[1].y));
        uint4 p1 = make_uint4(f2tf32(bV[0].z), f2tf32(bV[1].z),
                              f2tf32(bV[0].w), f2tf32(bV[1].w));
        *reinterpret_cast<uint4*>(dst)     = p0;
        *reinterpret_cast<uint4*>(dst + 4) = p1;
    };

    loadA(0); loadB(0);
    stsTile(0);
    __syncthreads();

    int buf = 0;
    for (int k0 = 16; k0 <= K; k0 += 16) {
        bool nxt = (k0 < K);
        if (nxt) { loadA(k0); loadB(k0); }
#pragma unroll
        for (int s = 0; s < 2; s++) {
            uint32_t afr[2][4], bfr[8][2];
            int pidx = (s << 2) + lc;
#pragma unroll
            for (int mf = 0; mf < 2; mf++) {
                int rb = wm * 32 + mf * 16 + lr;
                uint2 a01 = *reinterpret_cast<const uint2*>(&As[buf][rb][pidx * 2]);
                uint2 a23 = *reinterpret_cast<const uint2*>(&As[buf][rb + 8][pidx * 2]);
                afr[mf][0] = a01.x; afr[mf][1] = a23.x;
                afr[mf][2] = a01.y; afr[mf][3] = a23.y;
            }
#pragma unroll
            for (int nf = 0; nf < 8; nf++) {
                int cb = wn * 64 + nf * 8 + lr;
                uint2 b01 = *reinterpret_cast<const uint2*>(&Bs[buf][pidx][cb * 2]);
                bfr[nf][0] = b01.x; bfr[nf][1] = b01.y;
            }
#pragma unroll
            for (int mf = 0; mf < 2; mf++)
#pragma unroll
                for (int nf = 0; nf < 8; nf++)
                    mma_tf32(acc[mf][nf], afr[mf], bfr[nf]);
        }
        if (nxt) stsTile(buf ^ 1);
        __syncthreads();
        buf ^= 1;
    }

#pragma unroll
    for (int mf = 0; mf < 2; mf++) {
#pragma unroll
        for (int r2 = 0; r2 < 2; r2++) {
            int pos = m0 + wm * 32 + mf * 16 + lr + r2 * 8;
            if (pos >= cnt) continue;
            int crow = gather[pos];
#pragma unroll
            for (int nf = 0; nf < 8; nf++) {
#pragma unroll
                for (int c2 = 0; c2 < 2; c2++) {
                    int col = n0 + wn * 64 + nf * 8 + lc * 2 + c2;
                    size_t ci = (size_t)crow * Nc + col;
                    float val = acc[mf][nf][r2 * 2 + c2];
                    if (residual) val += residual[ci];
                    C[ci] = val;
                }
            }
        }
    }
}

// ---------------- per-head RMSNorm + RoPE ----------------
__global__ void qknorm_rope_kernel(float* __restrict__ x, const float* __restrict__ w,
                                   int heads, int nrows) {
    int row = blockIdx.x * 8 + (threadIdx.x >> 5);
    if (row >= nrows) return;
    int lane = threadIdx.x & 31;
    int n = row / heads;
    float* base = x + (size_t)row * PDH;
    float x1 = base[lane];
    float x2 = base[lane + 32];
    float s = x1 * x1 + x2 * x2;
#pragma unroll
    for (int off = 16; off > 0; off >>= 1) s += __shfl_xor_sync(0xffffffffu, s, off);
    float scale = rsqrtf(s / (float)PDH + P_EPS);
    x1 *= scale * w[lane];
    x2 *= scale * w[lane + 32];
    float c  = g_cosT[n * 32 + lane];
    float sn = g_sinT[n * 32 + lane];
    base[lane]      = x1 * c - x2 * sn;
    base[lane + 32] = x2 * c + x1 * sn;
}

// ---------------- tensor-core flash attention ----------------
__global__ __launch_bounds__(256, 2)
void attn_tc_kernel(const float* __restrict__ q, const float* __restrict__ k,
                    const float* __restrict__ v, float* __restrict__ o) {
    __shared__ uint32_t Ks[32][68];
    __shared__ uint32_t Vs[32][72];
    __shared__ uint32_t Ps[128][36];

    int qb = blockIdx.x, h = blockIdx.y;
    int kvh = h >> 2;
    int q0 = qb * 128;
    int tid = threadIdx.x;
    int lane = tid & 31;
    int w = tid >> 5;
    int lr = lane >> 2, lc = lane & 3;

    uint32_t qfr[8][4];
    {
        const float* qb_ = q + (size_t)(q0 + w * 16) * PD + h * PDH;
#pragma unroll
        for (int ks = 0; ks < 8; ks++) {
            int c = ks * 8 + lc;
            qfr[ks][0] = f2tf32(qb_[(size_t)lr * PD + c]);
            qfr[ks][1] = f2tf32(qb_[(size_t)(lr + 8) * PD + c]);
            qfr[ks][2] = f2tf32(qb_[(size_t)lr * PD + c + 4]);
            qfr[ks][3] = f2tf32(qb_[(size_t)(lr + 8) * PD + c + 4]);
        }
    }

    float accO[8][4];
#pragma unroll
    for (int nf = 0; nf < 8; nf++)
#pragma unroll
        for (int c = 0; c < 4; c++) accO[nf][c] = 0.0f;
    float m0 = -INFINITY, m1 = -INFINITY, l0 = 0.0f, l1 = 0.0f;
    const float scale = 0.125f;

    for (int t = 0; t < PN / 32; t++) {
#pragma unroll
        for (int it = 0; it < 2; it++) {
            int i = tid + it * 256;
            int kv = i >> 4, d4 = (i & 15) * 4;
            size_t gi = (size_t)(t * 32 + kv) * (PKV * PDH) + kvh * PDH + d4;
            float4 kf = *reinterpret_cast<const float4*>(&k[gi]);
            float4 vf = *reinterpret_cast<const float4*>(&v[gi]);
            uint4 kt = make_uint4(f2tf32(kf.x), f2tf32(kf.y), f2tf32(kf.z), f2tf32(kf.w));
            uint4 vt = make_uint4(f2tf32(vf.x), f2tf32(vf.y), f2tf32(vf.z), f2tf32(vf.w));
            *reinterpret_cast<uint4*>(&Ks[kv][d4]) = kt;
            *reinterpret_cast<uint4*>(&Vs[kv][d4]) = vt;
        }
        __syncthreads();

        float sacc[4][4];
#pragma unroll
        for (int nf = 0; nf < 4; nf++)
#pragma unroll
            for (int c = 0; c < 4; c++) sacc[nf][c] = 0.0f;
#pragma unroll
        for (int ks = 0; ks < 8; ks++) {
#pragma unroll
            for (int nf = 0; nf < 4; nf++) {
                uint32_t b[2];
                b[0] = Ks[nf * 8 + lr][ks * 8 + lc];
                b[1] = Ks[nf * 8 + lr][ks * 8 + lc + 4];
                mma_tf32(sacc[nf], qfr[ks], b);
            }
        }

        float mloc0 = -INFINITY, mloc1 = -INFINITY;
#pragma unroll
        for (int nf = 0; nf < 4; nf++) {
#pragma unroll
            for (int c = 0; c < 4; c++) sacc[nf][c] *= scale;
            mloc0 = fmaxf(mloc0, fmaxf(sacc[nf][0], sacc[nf][1]));
            mloc1 = fmaxf(mloc1, fmaxf(sacc[nf][2], sacc[nf][3]));
        }
        mloc0 = fmaxf(mloc0, __shfl_xor_sync(0xffffffffu, mloc0, 1));
        mloc0 = fmaxf(mloc0, __shfl_xor_sync(0xffffffffu, mloc0, 2));
        mloc1 = fmaxf(mloc1, __shfl_xor_sync(0xffffffffu, mloc1, 1));
        mloc1 = fmaxf(mloc1, __shfl_xor_sync(0xffffffffu, mloc1, 2));
        float mn0 = fmaxf(m0, mloc0), mn1 = fmaxf(m1, mloc1);
        float corr0 = __expf(m0 - mn0), corr1 = __expf(m1 - mn1);
        float ls0 = 0.0f, ls1 = 0.0f;
        int prow = w * 16 + lr;
#pragma unroll
        for (int nf = 0; nf < 4; nf++) {
            float p00 = __expf(sacc[nf][0] - mn0);
            float p01 = __expf(sacc[nf][1] - mn0);
            float p10 = __expf(sacc[nf][2] - mn1);
            float p11 = __expf(sacc[nf][3] - mn1);
            ls0 += p00 + p01;
            ls1 += p10 + p11;
            int col = nf * 8 + 2 * lc;
            *reinterpret_cast<uint2*>(&Ps[prow][col])     = make_uint2(f2tf32(p00), f2tf32(p01));
            *reinterpret_cast<uint2*>(&Ps[prow + 8][col]) = make_uint2(f2tf32(p10), f2tf32(p11));
        }
        ls0 += __shfl_xor_sync(0xffffffffu, ls0, 1);
        ls0 += __shfl_xor_sync(0xffffffffu, ls0, 2);
        ls1 += __shfl_xor_sync(0xffffffffu, ls1, 1);
        ls1 += __shfl_xor_sync(0xffffffffu, ls1, 2);
        l0 = l0 * corr0 + ls0;
        l1 = l1 * corr1 + ls1;
        m0 = mn0; m1 = mn1;
#pragma unroll
        for (int nf = 0; nf < 8; nf++) {
            accO[nf][0] *= corr0; accO[nf][1] *= corr0;
            accO[nf][2] *= corr1; accO[nf][3] *= corr1;
        }
        __syncthreads();

#pragma unroll
        for (int ks2 = 0; ks2 < 4; ks2++) {
            uint32_t a[4];
            a[0] = Ps[w * 16 + lr][ks2 * 8 + lc];
            a[1] = Ps[w * 16 + lr + 8][ks2 * 8 + lc];
            a[2] = Ps[w * 16 + lr][ks2 * 8 + lc + 4];
            a[3] = Ps[w * 16 + lr + 8][ks2 * 8 + lc + 4];
#pragma unroll
            for (int nf = 0; nf < 8; nf++) {
                uint32_t b[2];
                b[0] = Vs[ks2 * 8 + lc][nf * 8 + lr];
                b[1] = Vs[ks2 * 8 + lc + 4][nf * 8 + lr];
                mma_tf32(accO[nf], a, b);
            }
        }
        __syncthreads();
    }

    float il0 = 1.0f / l0, il1 = 1.0f / l1;
    int row0 = q0 + w * 16 + lr;
#pragma unroll
    for (int nf = 0; nf < 8; nf++) {
        int col = h * PDH + nf * 8 + 2 * lc;
        *reinterpret_cast<float2*>(&o[(size_t)row0 * PD + col]) =
            make_float2(accO[nf][0] * il0, accO[nf][1] * il0);
        *reinterpret_cast<float2*>(&o[(size_t)(row0 + 8) * PD + col]) =
            make_float2(accO[nf][2] * il1, accO[nf][3] * il1);
    }
}

// ---------------- fused state-update ----------------
__global__ void fuse1_kernel(const float* __restrict__ co, const float* __restrict__ velocity,
                             const float* __restrict__ o, const float* __restrict__ mu_cur,
                             const float* __restrict__ hidden_in,
                             float* __restrict__ out_vnext, float* __restrict__ hidmid) {
    size_t i = (size_t)blockIdx.x * blockDim.x + threadIdx.x;
    if (i >= (size_t)PN * PD) return;
    int n = (int)(i / PD), d = (int)(i % PD);
    const float* cor = co + (size_t)n * 3 * PD;
    float alpha = sigmoidf_(cor[d]);
    float beta  = fminf(softplusf_(cor[PD + d]), 2.0f);
    float gate  = sigmoidf_(cor[2 * PD + d]);
    float ov = o[i], mc = mu_cur[i], vel = velocity[i];
    float err = ov - mc;
    float vn = alpha * vel - beta * err;
    vn = fminf(fmaxf(vn, -10.0f), 10.0f);
    out_vnext[i] = vn;
    hidmid[i] = hidden_in[i] + ov + P_DT * gate * vn;
}

// ---------------- router ----------------
__global__ void router_kernel(const float* __restrict__ mu_cur, const float* __restrict__ w,
                              const int* __restrict__ token_ids) {
    int tkn = blockIdx.x * 8 + (threadIdx.x >> 5);
    if (tkn >= PN) return;
    int lane = threadIdx.x & 31;
    float lg[PE];
#pragma unroll
    for (int e = 0; e < PE; e++) lg[e] = 0.0f;
    const float* xr = mu_cur + (size_t)tkn * PD;
    for (int d = lane; d < PD; d += 32) {
        float xv = xr[d];
        const float* wr = w + (size_t)d * PE;
#pragma unroll
        for (int e = 0; e < PE; e++) lg[e] += xv * wr[e];
    }
#pragma unroll
    for (int e = 0; e < PE; e++) {
#pragma unroll
        for (int off = 16; off > 0; off >>= 1)
            lg[e] += __shfl_xor_sync(0xffffffffu, lg[e], off);
    }
    if (lane == 0) {
        int b = token_ids[tkn] % PE;
        lg[b] += P_BASE_SCALE;
        int best = 0; float bv = lg[0];
#pragma unroll
        for (int e = 1; e < PE; e++) {
            if (lg[e] > bv) { bv = lg[e]; best = e; }
        }
        int slot = atomicAdd(&g_ecount[best], 1);
        g_elist[best * PN + slot] = tkn;
    }
}

__global__ void midcombine_kernel() {
    size_t i = (size_t)blockIdx.x * blockDim.x + threadIdx.x;
    if (i >= (size_t)PN * PF) return;
    float gv = g_G[i];
    g_mid[i] = (gv / (1.0f + expf(-gv))) * g_U[i];
}

// ---------------- host launch ----------------
static inline void* sym_addr(const void* sym) {
    void* p = nullptr;
    cudaGetSymbolAddress(&p, sym);
    return p;
}

extern "C" void kernel_launch(void* const* d_in, const int* in_sizes, int n_in,
                              void* d_out, int out_size) {
    const float* hidden    = (const float*)d_in[0];
    const int*   positions = (const int*)d_in[1];
    const float* velocity  = (const float*)d_in[2];
    const int*   token_ids = (const int*)d_in[3];
    const float* mu_prev   = (const float*)d_in[4];
    const float* ln1_w     = (const float*)d_in[5];
    const float* ln2_w     = (const float*)d_in[6];
    const float* wq        = (const float*)d_in[7];
    const float* wk        = (const float*)d_in[8];
    const float* wv        = (const float*)d_in[9];
    const float* wo        = (const float*)d_in[10];
    const float* w_mu_q    = (const float*)d_in[11];
    const float* w_mu_k    = (const float*)d_in[12];
    const float* w_mu_v    = (const float*)d_in[13];
    const float* qnorm_w   = (const float*)d_in[14];
    const float* knorm_w   = (const float*)d_in[15];
    const float* dyn_mu    = (const float*)d_in[16];
    const float* dyn_proj  = (const float*)d_in[17];
    const float* ctrl_in_w = (const float*)d_in[18];
    const float* ctrl_in_b = (const float*)d_in[19];
    const float* ctrl_out_w= (const float*)d_in[20];
    const float* ctrl_out_b= (const float*)d_in[21];
    const float* mu_router = (const float*)d_in[22];
    const float* w_gate    = (const float*)d_in[23];
    const float* w_up      = (const float*)d_in[24];
    const float* w_down    = (const float*)d_in[25];

    float* out_hidden = (float*)d_out;
    float* out_vnext  = out_hidden + (size_t)PN * PD;
    float* out_mucur  = out_vnext  + (size_t)PN * PD;

    float* p_hnorm  = (float*)sym_addr(g_hnorm);
    float* p_q      = (float*)sym_addr(g_q);
    float* p_k      = (float*)sym_addr(g_k);
    float* p_v      = (float*)sym_addr(g_v);
    float* p_attno  = (float*)sym_addr(g_attno);
    float* p_o      = (float*)sym_addr(g_o);
    float* p_ctrl   = (float*)sym_addr(g_ctrl);
    float* p_co     = (float*)sym_addr(g_co);
    float* p_hidmid = (float*)sym_addr(g_hidmid);
    float* p_xnorm  = (float*)sym_addr(g_xnorm);
    float* p_G      = (float*)sym_addr(g_G);
    float* p_U      = (float*)sym_addr(g_U);
    float* p_mid    = (float*)sym_addr(g_mid);

    zero_counts_kernel<<<1, 32>>>();
    rope_table_kernel<<<(PN * 32 + 255) / 256, 256>>>(positions);
    rmsnorm_kernel<<<PN, 256>>>(hidden, ln1_w, p_hnorm);

    // QKV in ONE launch
    {
        GDesc dq { p_hnorm, mu_prev, wq, w_mu_q, nullptr, p_q, PH * PDH, 2 * PD, PD, 0 };
        GDesc dk { p_hnorm, mu_prev, wk, w_mu_k, nullptr, p_k, PKV * PDH, 2 * PD, PD, 0 };
        GDesc dv { p_hnorm, mu_prev, wv, w_mu_v, nullptr, p_v, PKV * PDH, 2 * PD, PD, 0 };
        tf32_gemm_multi<<<dim3(8, 16, 3), 256>>>(dq, dk, dv);
    }

    qknorm_rope_kernel<<<(PN * PH + 7) / 8, 256>>>(p_q, qnorm_w, PH, PN * PH);
    qknorm_rope_kernel<<<(PN * PKV + 7) / 8, 256>>>(p_k, knorm_w, PKV, PN * PKV);

    attn_tc_kernel<<<dim3(PN / 128, PH), 256>>>(p_q, p_k, p_v, p_attno);

    // o = attno @ wo
    {
        GDesc d { p_attno, nullptr, wo, nullptr, nullptr, p_o, PD, PD, PD, 0 };
        tf32_gemm_multi<<<dim3(8, 16, 1), 256>>>(d, d, d);
    }

    // dyn-proj and ctrl concurrently
    {
        GDesc dd { p_o, nullptr, dyn_proj, nullptr, dyn_mu, out_mucur, PD, PD, PD, 0 };
        GDesc dc { p_o, velocity, ctrl_in_w, ctrl_in_w + PD * PCH, ctrl_in_b, p_ctrl,
                   PCH, 2 * PD, PD, 2 };
        tf32_gemm_multi<<<dim3(8, 16, 2), 256>>>(dd, dc, dc);
    }

    // co = ctrl @ ctrl_out_w + ctrl_out_b
    {
        GDesc d { p_ctrl, nullptr, ctrl_out_w, nullptr, ctrl_out_b, p_co, 3 * PD, PCH, PCH, 0 };
        tf32_gemm_multi<<<dim3(24, 16, 1), 256>>>(d, d, d);
    }

    fuse1_kernel<<<(PN * PD + 255) / 256, 256>>>(p_co, velocity, p_o, out_mucur, hidden,
                                                 out_vnext, p_hidmid);

    rmsnorm_kernel<<<PN, 256>>>(p_hidmid, ln2_w, p_xnorm);
    router_kernel<<<(PN + 7) / 8, 256>>>(out_mucur, mu_router, token_ids);

    moe_gemm_kernel<<<dim3(32, 16, PE), 256>>>(p_xnorm, w_gate, w_up,
                                               (size_t)PD * PF, p_G, p_U,
                                               nullptr, PF, PD, 16);
    midcombine_kernel<<<(PN * PF + 255) / 256, 256>>>();

    moe_gemm_kernel<<<dim3(8, 16, PE), 256>>>(p_mid, w_down, nullptr,
                                              (size_t)PF * PD, out_hidden, nullptr,
                                              p_hidmid, PD, PF, 8);
}

// round 7
// speedup vs baseline: 1.0976x; 1.0976x over previous
#include <cuda_runtime.h>
#include <math.h>
#include <stdint.h>

// ---------------- problem constants ----------------
#define PN   2048
#define PD   1024
#define PH   16
#define PKV  4
#define PDH  64
#define PE   8
#define PF   2048
#define PCH  64
#define P_EPS 1e-6f
#define P_DT  0.1f
#define P_BASE_SCALE 10.0f

// ---------------- scratch ----------------
__device__ float g_hnorm[PN * PD];
__device__ float g_q[PN * PH * PDH];
__device__ float g_k[PN * PKV * PDH];
__device__ float g_v[PN * PKV * PDH];
__device__ float g_attno[PN * PD];
__device__ float g_o[PN * PD];
__device__ float g_ctrl[PN * PCH];
__device__ float g_co[PN * 3 * PD];
__device__ float g_hidmid[PN * PD];
__device__ float g_xnorm[PN * PD];
__device__ float g_G[PN * PF];
__device__ float g_U[PN * PF];
__device__ float g_mid[PN * PF];
__device__ float g_cosT[PN * 32];
__device__ float g_sinT[PN * 32];
__device__ int   g_elist[PE * PN];
__device__ int   g_ecount[PE];

// ---------------- helpers ----------------
__device__ __forceinline__ float sigmoidf_(float x) { return 1.0f / (1.0f + expf(-x)); }
__device__ __forceinline__ float softplusf_(float x) {
    return fmaxf(x, 0.0f) + log1pf(expf(-fabsf(x)));
}
__device__ __forceinline__ uint32_t f2tf32(float f) {
    uint32_t r; asm("cvt.rna.tf32.f32 %0, %1;" : "=r"(r) : "f"(f)); return r;
}
__device__ __forceinline__ void mma_tf32(float* d, const uint32_t* a, const uint32_t* b) {
    asm volatile(
        "mma.sync.aligned.m16n8k8.row.col.f32.tf32.tf32.f32 "
        "{%0,%1,%2,%3}, {%4,%5,%6,%7}, {%8,%9}, {%0,%1,%2,%3};"
        : "+f"(d[0]), "+f"(d[1]), "+f"(d[2]), "+f"(d[3])
        : "r"(a[0]), "r"(a[1]), "r"(a[2]), "r"(a[3]), "r"(b[0]), "r"(b[1]));
}

__global__ void zero_counts_kernel() {
    int t = threadIdx.x;
    if (t < PE) g_ecount[t] = 0;
}

__global__ void rope_table_kernel(const int* __restrict__ positions) {
    __shared__ float sm_inv[32];
    if (threadIdx.x < 32) {
        double inv = pow(10000.0, -((double)(2 * threadIdx.x)) / 64.0);
        sm_inv[threadIdx.x] = (float)inv;
    }
    __syncthreads();
    int i = blockIdx.x * 256 + threadIdx.x;
    if (i >= PN * 32) return;
    int n = i >> 5, f = i & 31;
    float ang = (float)positions[n] * sm_inv[f];
    float s, c;
    sincosf(ang, &s, &c);
    g_cosT[i] = c;
    g_sinT[i] = s;
}

__global__ void rmsnorm_kernel(const float* __restrict__ x, const float* __restrict__ w,
                               float* __restrict__ out) {
    int row = blockIdx.x;
    int tid = threadIdx.x;
    __shared__ float red[256];
    const float* xr = x + (size_t)row * PD;
    float s = 0.0f;
    for (int d = tid; d < PD; d += 256) { float v = xr[d]; s += v * v; }
    red[tid] = s; __syncthreads();
    for (int off = 128; off > 0; off >>= 1) {
        if (tid < off) red[tid] += red[tid + off];
        __syncthreads();
    }
    float scale = rsqrtf(red[0] / (float)PD + P_EPS);
    float* orow = out + (size_t)row * PD;
    for (int d = tid; d < PD; d += 256) orow[d] = xr[d] * scale * w[d];
}

// ---------------- multi-descriptor TF32 GEMM (round-5 layout, vectorized STS) ----------------
struct GDesc {
    const float* A; const float* A2;
    const float* B; const float* B2;
    const float* bias;
    float* C;
    int Nc; int K; int K1; int flags;    // flags bit1: SiLU
};

__global__ __launch_bounds__(256, 2)
void tf32_gemm_multi(GDesc d0, GDesc d1, GDesc d2) {
    __shared__ uint32_t As[2][128][20];
    __shared__ uint32_t Bs[2][16][136];

    GDesc d = (blockIdx.z == 0) ? d0 : ((blockIdx.z == 1) ? d1 : d2);
    int m0 = blockIdx.y * 128;
    int n0 = blockIdx.x * 128;
    if (n0 >= d.Nc) return;

    int tid  = threadIdx.x;
    int lane = tid & 31;
    int w    = tid >> 5;
    int wm   = w >> 1;
    int wn   = w & 1;

    int a_r  = tid >> 2;
    int a_kq = (tid & 3) * 4;
    int b_k  = tid >> 5;
    int b_nq = (tid & 31) * 4;

    float4 aV[2], bV[2];
    float acc[2][8][4];
#pragma unroll
    for (int mf = 0; mf < 2; mf++)
#pragma unroll
        for (int nf = 0; nf < 8; nf++)
#pragma unroll
            for (int c = 0; c < 4; c++) acc[mf][nf][c] = 0.0f;

    auto loadA = [&](int k0) {
        const float* Ap = d.A; int lda = d.K1; int kk = k0;
        if (k0 >= d.K1) { Ap = d.A2; lda = d.K - d.K1; kk = k0 - d.K1; }
#pragma unroll
        for (int i = 0; i < 2; i++) {
            int pos = m0 + a_r + i * 64;
            aV[i] = *reinterpret_cast<const float4*>(&Ap[(size_t)pos * lda + kk + a_kq]);
        }
    };
    auto loadB = [&](int k0) {
        const float* Bp = d.B; int kk = k0;
        if (k0 >= d.K1) { Bp = d.B2; kk = k0 - d.K1; }
        int col = n0 + b_nq;
#pragma unroll
        for (int i = 0; i < 2; i++) {
            if (col < d.Nc) {
                bV[i] = *reinterpret_cast<const float4*>(&Bp[(size_t)(kk + b_k + i * 8) * d.Nc + col]);
            } else {
                bV[i] = make_float4(0.f, 0.f, 0.f, 0.f);
            }
        }
    };
    auto stsTile = [&](int buf) {
#pragma unroll
        for (int i = 0; i < 2; i++) {
            int r = a_r + i * 64;
            uint4 av = make_uint4(f2tf32(aV[i].x), f2tf32(aV[i].y),
                                  f2tf32(aV[i].z), f2tf32(aV[i].w));
            *reinterpret_cast<uint4*>(&As[buf][r][a_kq]) = av;
        }
#pragma unroll
        for (int i = 0; i < 2; i++) {
            int kr = b_k + i * 8;
            uint4 bv = make_uint4(f2tf32(bV[i].x), f2tf32(bV[i].y),
                                  f2tf32(bV[i].z), f2tf32(bV[i].w));
            *reinterpret_cast<uint4*>(&Bs[buf][kr][b_nq]) = bv;
        }
    };

    loadA(0); loadB(0);
    stsTile(0);
    __syncthreads();

    int buf = 0;
    for (int k0 = 16; k0 <= d.K; k0 += 16) {
        bool nxt = (k0 < d.K);
        if (nxt) { loadA(k0); loadB(k0); }
#pragma unroll
        for (int s = 0; s < 2; s++) {
            uint32_t afr[2][4], bfr[8][2];
            int kk = s * 8 + (lane & 3);
#pragma unroll
            for (int mf = 0; mf < 2; mf++) {
                int rb = wm * 32 + mf * 16 + (lane >> 2);
                afr[mf][0] = As[buf][rb][kk];
                afr[mf][1] = As[buf][rb + 8][kk];
                afr[mf][2] = As[buf][rb][kk + 4];
                afr[mf][3] = As[buf][rb + 8][kk + 4];
            }
#pragma unroll
            for (int nf = 0; nf < 8; nf++) {
                int cb = wn * 64 + nf * 8 + (lane >> 2);
                bfr[nf][0] = Bs[buf][kk][cb];
                bfr[nf][1] = Bs[buf][kk + 4][cb];
            }
#pragma unroll
            for (int mf = 0; mf < 2; mf++)
#pragma unroll
                for (int nf = 0; nf < 8; nf++)
                    mma_tf32(acc[mf][nf], afr[mf], bfr[nf]);
        }
        if (nxt) stsTile(buf ^ 1);
        __syncthreads();
        buf ^= 1;
    }

#pragma unroll
    for (int mf = 0; mf < 2; mf++) {
#pragma unroll
        for (int r2 = 0; r2 < 2; r2++) {
            int crow = m0 + wm * 32 + mf * 16 + (lane >> 2) + r2 * 8;
#pragma unroll
            for (int nf = 0; nf < 8; nf++) {
#pragma unroll
                for (int c2 = 0; c2 < 2; c2++) {
                    int col = n0 + wn * 64 + nf * 8 + (lane & 3) * 2 + c2;
                    if (col >= d.Nc) continue;
                    size_t ci = (size_t)crow * d.Nc + col;
                    float val = acc[mf][nf][r2 * 2 + c2];
                    if (d.bias) val += d.bias[col];
                    if (d.flags & 2) val = val / (1.0f + expf(-val));
                    d.C[ci] = val;
                }
            }
        }
    }
}

// ---------------- MoE GEMM: grid.z = expert, gate/up split along x ----------------
__global__ __launch_bounds__(256, 2)
void moe_gemm_kernel(const float* __restrict__ A,
                     const float* __restrict__ Bg, const float* __restrict__ Bu,
                     size_t bStride, float* __restrict__ Cg, float* __restrict__ Cu,
                     const float* __restrict__ residual,
                     int Nc, int K, int xPart) {
    __shared__ uint32_t As[2][128][20];
    __shared__ uint32_t Bs[2][16][136];

    int e = blockIdx.z;
    int cnt = g_ecount[e];
    int m0 = blockIdx.y * 128;
    if (m0 >= cnt) return;
    int part = blockIdx.x / xPart;
    int n0 = (blockIdx.x % xPart) * 128;
    const float* B = (part ? Bu : Bg) + (size_t)e * bStride;
    float* C = part ? Cu : Cg;
    const int* gather = g_elist + e * PN;

    int tid  = threadIdx.x;
    int lane = tid & 31;
    int w    = tid >> 5;
    int wm   = w >> 1;
    int wn   = w & 1;

    int a_r  = tid >> 2;
    int a_kq = (tid & 3) * 4;
    int b_k  = tid >> 5;
    int b_nq = (tid & 31) * 4;

    float4 aV[2], bV[2];
    float acc[2][8][4];
#pragma unroll
    for (int mf = 0; mf < 2; mf++)
#pragma unroll
        for (int nf = 0; nf < 8; nf++)
#pragma unroll
            for (int c = 0; c < 4; c++) acc[mf][nf][c] = 0.0f;

    auto loadA = [&](int k0) {
#pragma unroll
        for (int i = 0; i < 2; i++) {
            int pos = m0 + a_r + i * 64;
            if (pos < cnt) {
                int ar = gather[pos];
                aV[i] = *reinterpret_cast<const float4*>(&A[(size_t)ar * K + k0 + a_kq]);
            } else {
                aV[i] = make_float4(0.f, 0.f, 0.f, 0.f);
            }
        }
    };
    auto loadB = [&](int k0) {
        int col = n0 + b_nq;
#pragma unroll
        for (int i = 0; i < 2; i++)
            bV[i] = *reinterpret_cast<const float4*>(&B[(size_t)(k0 + b_k + i * 8) * Nc + col]);
    };
    auto stsTile = [&](int buf) {
#pragma unroll
        for (int i = 0; i < 2; i++) {
            int r = a_r + i * 64;
            uint4 av = make_uint4(f2tf32(aV[i].x), f2tf32(aV[i].y),
                                  f2tf32(aV[i].z), f2tf32(aV[i].w));
            *reinterpret_cast<uint4*>(&As[buf][r][a_kq]) = av;
        }
#pragma unroll
        for (int i = 0; i < 2; i++) {
            int kr = b_k + i * 8;
            uint4 bv = make_uint4(f2tf32(bV[i].x), f2tf32(bV[i].y),
                                  f2tf32(bV[i].z), f2tf32(bV[i].w));
            *reinterpret_cast<uint4*>(&Bs[buf][kr][b_nq]) = bv;
        }
    };

    loadA(0); loadB(0);
    stsTile(0);
    __syncthreads();

    int buf = 0;
    for (int k0 = 16; k0 <= K; k0 += 16) {
        bool nxt = (k0 < K);
        if (nxt) { loadA(k0); loadB(k0); }
#pragma unroll
        for (int s = 0; s < 2; s++) {
            uint32_t afr[2][4], bfr[8][2];
            int kk = s * 8 + (lane & 3);
#pragma unroll
            for (int mf = 0; mf < 2; mf++) {
                int rb = wm * 32 + mf * 16 + (lane >> 2);
                afr[mf][0] = As[buf][rb][kk];
                afr[mf][1] = As[buf][rb + 8][kk];
                afr[mf][2] = As[buf][rb][kk + 4];
                afr[mf][3] = As[buf][rb + 8][kk + 4];
            }
#pragma unroll
            for (int nf = 0; nf < 8; nf++) {
                int cb = wn * 64 + nf * 8 + (lane >> 2);
                bfr[nf][0] = Bs[buf][kk][cb];
                bfr[nf][1] = Bs[buf][kk + 4][cb];
            }
#pragma unroll
            for (int mf = 0; mf < 2; mf++)
#pragma unroll
                for (int nf = 0; nf < 8; nf++)
                    mma_tf32(acc[mf][nf], afr[mf], bfr[nf]);
        }
        if (nxt) stsTile(buf ^ 1);
        __syncthreads();
        buf ^= 1;
    }

#pragma unroll
    for (int mf = 0; mf < 2; mf++) {
#pragma unroll
        for (int r2 = 0; r2 < 2; r2++) {
            int pos = m0 + wm * 32 + mf * 16 + (lane >> 2) + r2 * 8;
            if (pos >= cnt) continue;
            int crow = gather[pos];
#pragma unroll
            for (int nf = 0; nf < 8; nf++) {
#pragma unroll
                for (int c2 = 0; c2 < 2; c2++) {
                    int col = n0 + wn * 64 + nf * 8 + (lane & 3) * 2 + c2;
                    size_t ci = (size_t)crow * Nc + col;
                    float val = acc[mf][nf][r2 * 2 + c2];
                    if (residual) val += residual[ci];
                    C[ci] = val;
                }
            }
        }
    }
}

// ---------------- per-head RMSNorm + RoPE ----------------
__global__ void qknorm_rope_kernel(float* __restrict__ x, const float* __restrict__ w,
                                   int heads, int nrows) {
    int row = blockIdx.x * 8 + (threadIdx.x >> 5);
    if (row >= nrows) return;
    int lane = threadIdx.x & 31;
    int n = row / heads;
    float* base = x + (size_t)row * PDH;
    float x1 = base[lane];
    float x2 = base[lane + 32];
    float s = x1 * x1 + x2 * x2;
#pragma unroll
    for (int off = 16; off > 0; off >>= 1) s += __shfl_xor_sync(0xffffffffu, s, off);
    float scale = rsqrtf(s / (float)PDH + P_EPS);
    x1 *= scale * w[lane];
    x2 *= scale * w[lane + 32];
    float c  = g_cosT[n * 32 + lane];
    float sn = g_sinT[n * 32 + lane];
    base[lane]      = x1 * c - x2 * sn;
    base[lane + 32] = x2 * c + x1 * sn;
}

// ---------------- tensor-core flash attention ----------------
__global__ __launch_bounds__(256, 2)
void attn_tc_kernel(const float* __restrict__ q, const float* __restrict__ k,
                    const float* __restrict__ v, float* __restrict__ o) {
    __shared__ uint32_t Ks[32][68];
    __shared__ uint32_t Vs[32][72];
    __shared__ uint32_t Ps[128][36];

    int qb = blockIdx.x, h = blockIdx.y;
    int kvh = h >> 2;
    int q0 = qb * 128;
    int tid = threadIdx.x;
    int lane = tid & 31;
    int w = tid >> 5;
    int lr = lane >> 2, lc = lane & 3;

    uint32_t qfr[8][4];
    {
        const float* qb_ = q + (size_t)(q0 + w * 16) * PD + h * PDH;
#pragma unroll
        for (int ks = 0; ks < 8; ks++) {
            int c = ks * 8 + lc;
            qfr[ks][0] = f2tf32(qb_[(size_t)lr * PD + c]);
            qfr[ks][1] = f2tf32(qb_[(size_t)(lr + 8) * PD + c]);
            qfr[ks][2] = f2tf32(qb_[(size_t)lr * PD + c + 4]);
            qfr[ks][3] = f2tf32(qb_[(size_t)(lr + 8) * PD + c + 4]);
        }
    }

    float accO[8][4];
#pragma unroll
    for (int nf = 0; nf < 8; nf++)
#pragma unroll
        for (int c = 0; c < 4; c++) accO[nf][c] = 0.0f;
    float m0 = -INFINITY, m1 = -INFINITY, l0 = 0.0f, l1 = 0.0f;
    const float scale = 0.125f;

    for (int t = 0; t < PN / 32; t++) {
#pragma unroll
        for (int it = 0; it < 2; it++) {
            int i = tid + it * 256;
            int kv = i >> 4, d4 = (i & 15) * 4;
            size_t gi = (size_t)(t * 32 + kv) * (PKV * PDH) + kvh * PDH + d4;
            float4 kf = *reinterpret_cast<const float4*>(&k[gi]);
            float4 vf = *reinterpret_cast<const float4*>(&v[gi]);
            uint4 kt = make_uint4(f2tf32(kf.x), f2tf32(kf.y), f2tf32(kf.z), f2tf32(kf.w));
            uint4 vt = make_uint4(f2tf32(vf.x), f2tf32(vf.y), f2tf32(vf.z), f2tf32(vf.w));
            *reinterpret_cast<uint4*>(&Ks[kv][d4]) = kt;
            *reinterpret_cast<uint4*>(&Vs[kv][d4]) = vt;
        }
        __syncthreads();

        float sacc[4][4];
#pragma unroll
        for (int nf = 0; nf < 4; nf++)
#pragma unroll
            for (int c = 0; c < 4; c++) sacc[nf][c] = 0.0f;
#pragma unroll
        for (int ks = 0; ks < 8; ks++) {
#pragma unroll
            for (int nf = 0; nf < 4; nf++) {
                uint32_t b[2];
                b[0] = Ks[nf * 8 + lr][ks * 8 + lc];
                b[1] = Ks[nf * 8 + lr][ks * 8 + lc + 4];
                mma_tf32(sacc[nf], qfr[ks], b);
            }
        }

        float mloc0 = -INFINITY, mloc1 = -INFINITY;
#pragma unroll
        for (int nf = 0; nf < 4; nf++) {
#pragma unroll
            for (int c = 0; c < 4; c++) sacc[nf][c] *= scale;
            mloc0 = fmaxf(mloc0, fmaxf(sacc[nf][0], sacc[nf][1]));
            mloc1 = fmaxf(mloc1, fmaxf(sacc[nf][2], sacc[nf][3]));
        }
        mloc0 = fmaxf(mloc0, __shfl_xor_sync(0xffffffffu, mloc0, 1));
        mloc0 = fmaxf(mloc0, __shfl_xor_sync(0xffffffffu, mloc0, 2));
        mloc1 = fmaxf(mloc1, __shfl_xor_sync(0xffffffffu, mloc1, 1));
        mloc1 = fmaxf(mloc1, __shfl_xor_sync(0xffffffffu, mloc1, 2));
        float mn0 = fmaxf(m0, mloc0), mn1 = fmaxf(m1, mloc1);
        float corr0 = __expf(m0 - mn0), corr1 = __expf(m1 - mn1);
        float ls0 = 0.0f, ls1 = 0.0f;
        int prow = w * 16 + lr;
#pragma unroll
        for (int nf = 0; nf < 4; nf++) {
            float p00 = __expf(sacc[nf][0] - mn0);
            float p01 = __expf(sacc[nf][1] - mn0);
            float p10 = __expf(sacc[nf][2] - mn1);
            float p11 = __expf(sacc[nf][3] - mn1);
            ls0 += p00 + p01;
            ls1 += p10 + p11;
            int col = nf * 8 + 2 * lc;
            *reinterpret_cast<uint2*>(&Ps[prow][col])     = make_uint2(f2tf32(p00), f2tf32(p01));
            *reinterpret_cast<uint2*>(&Ps[prow + 8][col]) = make_uint2(f2tf32(p10), f2tf32(p11));
        }
        ls0 += __shfl_xor_sync(0xffffffffu, ls0, 1);
        ls0 += __shfl_xor_sync(0xffffffffu, ls0, 2);
        ls1 += __shfl_xor_sync(0xffffffffu, ls1, 1);
        ls1 += __shfl_xor_sync(0xffffffffu, ls1, 2);
        l0 = l0 * corr0 + ls0;
        l1 = l1 * corr1 + ls1;
        m0 = mn0; m1 = mn1;
#pragma unroll
        for (int nf = 0; nf < 8; nf++) {
            accO[nf][0] *= corr0; accO[nf][1] *= corr0;
            accO[nf][2] *= corr1; accO[nf][3] *= corr1;
        }
        __syncthreads();

#pragma unroll
        for (int ks2 = 0; ks2 < 4; ks2++) {
            uint32_t a[4];
            a[0] = Ps[w * 16 + lr][ks2 * 8 + lc];
            a[1] = Ps[w * 16 + lr + 8][ks2 * 8 + lc];
            a[2] = Ps[w * 16 + lr][ks2 * 8 + lc + 4];
            a[3] = Ps[w * 16 + lr + 8][ks2 * 8 + lc + 4];
#pragma unroll
            for (int nf = 0; nf < 8; nf++) {
                uint32_t b[2];
                b[0] = Vs[ks2 * 8 + lc][nf * 8 + lr];
                b[1] = Vs[ks2 * 8 + lc + 4][nf * 8 + lr];
                mma_tf32(accO[nf], a, b);
            }
        }
        __syncthreads();
    }

    float il0 = 1.0f / l0, il1 = 1.0f / l1;
    int row0 = q0 + w * 16 + lr;
#pragma unroll
    for (int nf = 0; nf < 8; nf++) {
        int col = h * PDH + nf * 8 + 2 * lc;
        *reinterpret_cast<float2*>(&o[(size_t)row0 * PD + col]) =
            make_float2(accO[nf][0] * il0, accO[nf][1] * il0);
        *reinterpret_cast<float2*>(&o[(size_t)(row0 + 8) * PD + col]) =
            make_float2(accO[nf][2] * il1, accO[nf][3] * il1);
    }
}

// ---------------- fused state-update ----------------
__global__ void fuse1_kernel(const float* __restrict__ co, const float* __restrict__ velocity,
                             const float* __restrict__ o, const float* __restrict__ mu_cur,
                             const float* __restrict__ hidden_in,
                             float* __restrict__ out_vnext, float* __restrict__ hidmid) {
    size_t i = (size_t)blockIdx.x * blockDim.x + threadIdx.x;
    if (i >= (size_t)PN * PD) return;
    int n = (int)(i / PD), d = (int)(i % PD);
    const float* cor = co + (size_t)n * 3 * PD;
    float alpha = sigmoidf_(cor[d]);
    float beta  = fminf(softplusf_(cor[PD + d]), 2.0f);
    float gate  = sigmoidf_(cor[2 * PD + d]);
    float ov = o[i], mc = mu_cur[i], vel = velocity[i];
    float err = ov - mc;
    float vn = alpha * vel - beta * err;
    vn = fminf(fmaxf(vn, -10.0f), 10.0f);
    out_vnext[i] = vn;
    hidmid[i] = hidden_in[i] + ov + P_DT * gate * vn;
}

// ---------------- router ----------------
__global__ void router_kernel(const float* __restrict__ mu_cur, const float* __restrict__ w,
                              const int* __restrict__ token_ids) {
    int tkn = blockIdx.x * 8 + (threadIdx.x >> 5);
    if (tkn >= PN) return;
    int lane = threadIdx.x & 31;
    float lg[PE];
#pragma unroll
    for (int e = 0; e < PE; e++) lg[e] = 0.0f;
    const float* xr = mu_cur + (size_t)tkn * PD;
    for (int d = lane; d < PD; d += 32) {
        float xv = xr[d];
        const float* wr = w + (size_t)d * PE;
#pragma unroll
        for (int e = 0; e < PE; e++) lg[e] += xv * wr[e];
    }
#pragma unroll
    for (int e = 0; e < PE; e++) {
#pragma unroll
        for (int off = 16; off > 0; off >>= 1)
            lg[e] += __shfl_xor_sync(0xffffffffu, lg[e], off);
    }
    if (lane == 0) {
        int b = token_ids[tkn] % PE;
        lg[b] += P_BASE_SCALE;
        int best = 0; float bv = lg[0];
#pragma unroll
        for (int e = 1; e < PE; e++) {
            if (lg[e] > bv) { bv = lg[e]; best = e; }
        }
        int slot = atomicAdd(&g_ecount[best], 1);
        g_elist[best * PN + slot] = tkn;
    }
}

__global__ void midcombine_kernel() {
    size_t i = (size_t)blockIdx.x * blockDim.x + threadIdx.x;
    if (i >= (size_t)PN * PF) return;
    float gv = g_G[i];
    g_mid[i] = (gv / (1.0f + expf(-gv))) * g_U[i];
}

// ---------------- host launch ----------------
static inline void* sym_addr(const void* sym) {
    void* p = nullptr;
    cudaGetSymbolAddress(&p, sym);
    return p;
}

extern "C" void kernel_launch(void* const* d_in, const int* in_sizes, int n_in,
                              void* d_out, int out_size) {
    const float* hidden    = (const float*)d_in[0];
    const int*   positions = (const int*)d_in[1];
    const float* velocity  = (const float*)d_in[2];
    const int*   token_ids = (const int*)d_in[3];
    const float* mu_prev   = (const float*)d_in[4];
    const float* ln1_w     = (const float*)d_in[5];
    const float* ln2_w     = (const float*)d_in[6];
    const float* wq        = (const float*)d_in[7];
    const float* wk        = (const float*)d_in[8];
    const float* wv        = (const float*)d_in[9];
    const float* wo        = (const float*)d_in[10];
    const float* w_mu_q    = (const float*)d_in[11];
    const float* w_mu_k    = (const float*)d_in[12];
    const float* w_mu_v    = (const float*)d_in[13];
    const float* qnorm_w   = (const float*)d_in[14];
    const float* knorm_w   = (const float*)d_in[15];
    const float* dyn_mu    = (const float*)d_in[16];
    const float* dyn_proj  = (const float*)d_in[17];
    const float* ctrl_in_w = (const float*)d_in[18];
    const float* ctrl_in_b = (const float*)d_in[19];
    const float* ctrl_out_w= (const float*)d_in[20];
    const float* ctrl_out_b= (const float*)d_in[21];
    const float* mu_router = (const float*)d_in[22];
    const float* w_gate    = (const float*)d_in[23];
    const float* w_up      = (const float*)d_in[24];
    const float* w_down    = (const float*)d_in[25];

    float* out_hidden = (float*)d_out;
    float* out_vnext  = out_hidden + (size_t)PN * PD;
    float* out_mucur  = out_vnext  + (size_t)PN * PD;

    float* p_hnorm  = (float*)sym_addr(g_hnorm);
    float* p_q      = (float*)sym_addr(g_q);
    float* p_k      = (float*)sym_addr(g_k);
    float* p_v      = (float*)sym_addr(g_v);
    float* p_attno  = (float*)sym_addr(g_attno);
    float* p_o      = (float*)sym_addr(g_o);
    float* p_ctrl   = (float*)sym_addr(g_ctrl);
    float* p_co     = (float*)sym_addr(g_co);
    float* p_hidmid = (float*)sym_addr(g_hidmid);
    float* p_xnorm  = (float*)sym_addr(g_xnorm);
    float* p_G      = (float*)sym_addr(g_G);
    float* p_U      = (float*)sym_addr(g_U);
    float* p_mid    = (float*)sym_addr(g_mid);

    zero_counts_kernel<<<1, 32>>>();
    rope_table_kernel<<<(PN * 32 + 255) / 256, 256>>>(positions);
    rmsnorm_kernel<<<PN, 256>>>(hidden, ln1_w, p_hnorm);

    // QKV in ONE launch
    {
        GDesc dq { p_hnorm, mu_prev, wq, w_mu_q, nullptr, p_q, PH * PDH, 2 * PD, PD, 0 };
        GDesc dk { p_hnorm, mu_prev, wk, w_mu_k, nullptr, p_k, PKV * PDH, 2 * PD, PD, 0 };
        GDesc dv { p_hnorm, mu_prev, wv, w_mu_v, nullptr, p_v, PKV * PDH, 2 * PD, PD, 0 };
        tf32_gemm_multi<<<dim3(8, 16, 3), 256>>>(dq, dk, dv);
    }

    qknorm_rope_kernel<<<(PN * PH + 7) / 8, 256>>>(p_q, qnorm_w, PH, PN * PH);
    qknorm_rope_kernel<<<(PN * PKV + 7) / 8, 256>>>(p_k, knorm_w, PKV, PN * PKV);

    attn_tc_kernel<<<dim3(PN / 128, PH), 256>>>(p_q, p_k, p_v, p_attno);

    // o = attno @ wo
    {
        GDesc d { p_attno, nullptr, wo, nullptr, nullptr, p_o, PD, PD, PD, 0 };
        tf32_gemm_multi<<<dim3(8, 16, 1), 256>>>(d, d, d);
    }

    // dyn-proj and ctrl concurrently
    {
        GDesc dd { p_o, nullptr, dyn_proj, nullptr, dyn_mu, out_mucur, PD, PD, PD, 0 };
        GDesc dc { p_o, velocity, ctrl_in_w, ctrl_in_w + PD * PCH, ctrl_in_b, p_ctrl,
                   PCH, 2 * PD, PD, 2 };
        tf32_gemm_multi<<<dim3(8, 16, 2), 256>>>(dd, dc, dc);
    }

    // co = ctrl @ ctrl_out_w + ctrl_out_b
    {
        GDesc d { p_ctrl, nullptr, ctrl_out_w, nullptr, ctrl_out_b, p_co, 3 * PD, PCH, PCH, 0 };
        tf32_gemm_multi<<<dim3(24, 16, 1), 256>>>(d, d, d);
    }

    fuse1_kernel<<<(PN * PD + 255) / 256, 256>>>(p_co, velocity, p_o, out_mucur, hidden,
                                                 out_vnext, p_hidmid);

    rmsnorm_kernel<<<PN, 256>>>(p_hidmid, ln2_w, p_xnorm);
    router_kernel<<<(PN + 7) / 8, 256>>>(out_mucur, mu_router, token_ids);

    moe_gemm_kernel<<<dim3(32, 16, PE), 256>>>(p_xnorm, w_gate, w_up,
                                               (size_t)PD * PF, p_G, p_U,
                                               nullptr, PF, PD, 16);
    midcombine_kernel<<<(PN * PF + 255) / 256, 256>>>();

    moe_gemm_kernel<<<dim3(8, 16, PE), 256>>>(p_mid, w_down, nullptr,
                                              (size_t)PF * PD, out_hidden, nullptr,
                                              p_hidmid, PD, PF, 8);
}

// round 8
// speedup vs baseline: 1.1454x; 1.0436x over previous
#include <cuda_runtime.h>
#include <math.h>
#include <stdint.h>

// ---------------- problem constants ----------------
#define PN   2048
#define PD   1024
#define PH   16
#define PKV  4
#define PDH  64
#define PE   8
#define PF   2048
#define PCH  64
#define P_EPS 1e-6f
#define P_DT  0.1f
#define P_BASE_SCALE 10.0f

// GEMM k-tile and smem geometry (dynamic smem)
#define KT      32
#define ASTR    36                    // A row stride (words): frag bank (4*lr+lc) distinct
#define BSTR    136                   // B row stride (words): frag bank (8*lc+lr) distinct
#define ASZ     (128 * ASTR)          // 4608 words
#define BSZ     (KT * BSTR)           // 4352 words
#define GEMM_SMEM_BYTES ((2 * ASZ + 2 * BSZ) * 4)   // 71680 B

// ---------------- scratch ----------------
__device__ float g_hnorm[PN * PD];
__device__ float g_q[PN * PH * PDH];
__device__ float g_k[PN * PKV * PDH];
__device__ float g_v[PN * PKV * PDH];
__device__ float g_attno[PN * PD];
__device__ float g_o[PN * PD];
__device__ float g_ctrl[PN * PCH];
__device__ float g_co[PN * 3 * PD];
__device__ float g_hidmid[PN * PD];
__device__ float g_xnorm[PN * PD];
__device__ float g_G[PN * PF];
__device__ float g_U[PN * PF];
__device__ float g_mid[PN * PF];
__device__ float g_cosT[PN * 32];
__device__ float g_sinT[PN * 32];
__device__ int   g_elist[PE * PN];
__device__ int   g_ecount[PE];

// ---------------- helpers ----------------
__device__ __forceinline__ float sigmoidf_(float x) { return 1.0f / (1.0f + expf(-x)); }
__device__ __forceinline__ float softplusf_(float x) {
    return fmaxf(x, 0.0f) + log1pf(expf(-fabsf(x)));
}
__device__ __forceinline__ uint32_t f2tf32(float f) {
    uint32_t r; asm("cvt.rna.tf32.f32 %0, %1;" : "=r"(r) : "f"(f)); return r;
}
__device__ __forceinline__ void mma_tf32(float* d, const uint32_t* a, const uint32_t* b) {
    asm volatile(
        "mma.sync.aligned.m16n8k8.row.col.f32.tf32.tf32.f32 "
        "{%0,%1,%2,%3}, {%4,%5,%6,%7}, {%8,%9}, {%0,%1,%2,%3};"
        : "+f"(d[0]), "+f"(d[1]), "+f"(d[2]), "+f"(d[3])
        : "r"(a[0]), "r"(a[1]), "r"(a[2]), "r"(a[3]), "r"(b[0]), "r"(b[1]));
}

__global__ void zero_counts_kernel() {
    int t = threadIdx.x;
    if (t < PE) g_ecount[t] = 0;
}

__global__ void rope_table_kernel(const int* __restrict__ positions) {
    __shared__ float sm_inv[32];
    if (threadIdx.x < 32) {
        double inv = pow(10000.0, -((double)(2 * threadIdx.x)) / 64.0);
        sm_inv[threadIdx.x] = (float)inv;
    }
    __syncthreads();
    int i = blockIdx.x * 256 + threadIdx.x;
    if (i >= PN * 32) return;
    int n = i >> 5, f = i & 31;
    float ang = (float)positions[n] * sm_inv[f];
    float s, c;
    sincosf(ang, &s, &c);
    g_cosT[i] = c;
    g_sinT[i] = s;
}

__global__ void rmsnorm_kernel(const float* __restrict__ x, const float* __restrict__ w,
                               float* __restrict__ out) {
    int row = blockIdx.x;
    int tid = threadIdx.x;
    __shared__ float red[256];
    const float* xr = x + (size_t)row * PD;
    float s = 0.0f;
    for (int d = tid; d < PD; d += 256) { float v = xr[d]; s += v * v; }
    red[tid] = s; __syncthreads();
    for (int off = 128; off > 0; off >>= 1) {
        if (tid < off) red[tid] += red[tid + off];
        __syncthreads();
    }
    float scale = rsqrtf(red[0] / (float)PD + P_EPS);
    float* orow = out + (size_t)row * PD;
    for (int d = tid; d < PD; d += 256) orow[d] = xr[d] * scale * w[d];
}

// ---------------- multi-descriptor TF32 GEMM, k-tile=32, dynamic smem ----------------
struct GDesc {
    const float* A; const float* A2;
    const float* B; const float* B2;
    const float* bias;
    float* C;
    int Nc; int K; int K1; int flags;    // flags bit1: SiLU
};

__global__ __launch_bounds__(256, 2)
void tf32_gemm_multi(GDesc d0, GDesc d1, GDesc d2) {
    extern __shared__ uint32_t sm[];
    uint32_t* Asm = sm;                    // [2][128][ASTR]
    uint32_t* Bsm = sm + 2 * ASZ;          // [2][KT][BSTR]
#define AS_(b, r, k) Asm[(b) * ASZ + (r) * ASTR + (k)]
#define BS_(b, r, n) Bsm[(b) * BSZ + (r) * BSTR + (n)]

    GDesc d = (blockIdx.z == 0) ? d0 : ((blockIdx.z == 1) ? d1 : d2);
    int m0 = blockIdx.y * 128;
    int n0 = blockIdx.x * 128;
    if (n0 >= d.Nc) return;

    int tid  = threadIdx.x;
    int lane = tid & 31;
    int w    = tid >> 5;
    int wm   = w >> 1;
    int wn   = w & 1;

    int a_r  = tid >> 2;            // 0..63 (and +64)
    int a_kq = (tid & 3) * 4;       // {0,4,8,12} (and +16)
    int b_k  = tid >> 5;            // 0..7 (rows +8,+16,+24)
    int b_nq = (tid & 31) * 4;

    float4 aV[4], bV[4];
    float acc[2][8][4];
#pragma unroll
    for (int mf = 0; mf < 2; mf++)
#pragma unroll
        for (int nf = 0; nf < 8; nf++)
#pragma unroll
            for (int c = 0; c < 4; c++) acc[mf][nf][c] = 0.0f;

    auto loadA = [&](int k0) {
        const float* Ap = d.A; int lda = d.K1; int kk = k0;
        if (k0 >= d.K1) { Ap = d.A2; lda = d.K - d.K1; kk = k0 - d.K1; }
#pragma unroll
        for (int i = 0; i < 2; i++) {
            int pos = m0 + a_r + i * 64;
            const float* row = &Ap[(size_t)pos * lda + kk + a_kq];
            aV[i * 2 + 0] = *reinterpret_cast<const float4*>(row);
            aV[i * 2 + 1] = *reinterpret_cast<const float4*>(row + 16);
        }
    };
    auto loadB = [&](int k0) {
        const float* Bp = d.B; int kk = k0;
        if (k0 >= d.K1) { Bp = d.B2; kk = k0 - d.K1; }
        int col = n0 + b_nq;
#pragma unroll
        for (int i = 0; i < 4; i++) {
            if (col < d.Nc) {
                bV[i] = *reinterpret_cast<const float4*>(&Bp[(size_t)(kk + b_k + i * 8) * d.Nc + col]);
            } else {
                bV[i] = make_float4(0.f, 0.f, 0.f, 0.f);
            }
        }
    };
    auto stsTile = [&](int buf) {
#pragma unroll
        for (int i = 0; i < 2; i++) {
            int r = a_r + i * 64;
#pragma unroll
            for (int j = 0; j < 2; j++) {
                float4 av = aV[i * 2 + j];
                uint4 at = make_uint4(f2tf32(av.x), f2tf32(av.y), f2tf32(av.z), f2tf32(av.w));
                *reinterpret_cast<uint4*>(&AS_(buf, r, a_kq + j * 16)) = at;
            }
        }
#pragma unroll
        for (int i = 0; i < 4; i++) {
            uint4 bt = make_uint4(f2tf32(bV[i].x), f2tf32(bV[i].y),
                                  f2tf32(bV[i].z), f2tf32(bV[i].w));
            *reinterpret_cast<uint4*>(&BS_(buf, b_k + i * 8, b_nq)) = bt;
        }
    };

    loadA(0); loadB(0);
    stsTile(0);
    __syncthreads();

    int buf = 0;
    for (int k0 = KT; k0 <= d.K; k0 += KT) {
        bool nxt = (k0 < d.K);
        if (nxt) { loadA(k0); loadB(k0); }
#pragma unroll
        for (int s = 0; s < 4; s++) {
            uint32_t afr[2][4], bfr[8][2];
            int kk = s * 8 + (lane & 3);
#pragma unroll
            for (int mf = 0; mf < 2; mf++) {
                int rb = wm * 32 + mf * 16 + (lane >> 2);
                afr[mf][0] = AS_(buf, rb, kk);
                afr[mf][1] = AS_(buf, rb + 8, kk);
                afr[mf][2] = AS_(buf, rb, kk + 4);
                afr[mf][3] = AS_(buf, rb + 8, kk + 4);
            }
#pragma unroll
            for (int nf = 0; nf < 8; nf++) {
                int cb = wn * 64 + nf * 8 + (lane >> 2);
                bfr[nf][0] = BS_(buf, kk, cb);
                bfr[nf][1] = BS_(buf, kk + 4, cb);
            }
#pragma unroll
            for (int mf = 0; mf < 2; mf++)
#pragma unroll
                for (int nf = 0; nf < 8; nf++)
                    mma_tf32(acc[mf][nf], afr[mf], bfr[nf]);
        }
        if (nxt) stsTile(buf ^ 1);
        __syncthreads();
        buf ^= 1;
    }

#pragma unroll
    for (int mf = 0; mf < 2; mf++) {
#pragma unroll
        for (int r2 = 0; r2 < 2; r2++) {
            int crow = m0 + wm * 32 + mf * 16 + (lane >> 2) + r2 * 8;
#pragma unroll
            for (int nf = 0; nf < 8; nf++) {
#pragma unroll
                for (int c2 = 0; c2 < 2; c2++) {
                    int col = n0 + wn * 64 + nf * 8 + (lane & 3) * 2 + c2;
                    if (col >= d.Nc) continue;
                    size_t ci = (size_t)crow * d.Nc + col;
                    float val = acc[mf][nf][r2 * 2 + c2];
                    if (d.bias) val += d.bias[col];
                    if (d.flags & 2) val = val / (1.0f + expf(-val));
                    d.C[ci] = val;
                }
            }
        }
    }
}

// ---------------- MoE GEMM: grid.z = expert, gate/up split along x, k-tile=32 ----------------
__global__ __launch_bounds__(256, 2)
void moe_gemm_kernel(const float* __restrict__ A,
                     const float* __restrict__ Bg, const float* __restrict__ Bu,
                     size_t bStride, float* __restrict__ Cg, float* __restrict__ Cu,
                     const float* __restrict__ residual,
                     int Nc, int K, int xPart) {
    extern __shared__ uint32_t sm[];
    uint32_t* Asm = sm;
    uint32_t* Bsm = sm + 2 * ASZ;

    int e = blockIdx.z;
    int cnt = g_ecount[e];
    int m0 = blockIdx.y * 128;
    if (m0 >= cnt) return;
    int part = blockIdx.x / xPart;
    int n0 = (blockIdx.x % xPart) * 128;
    const float* B = (part ? Bu : Bg) + (size_t)e * bStride;
    float* C = part ? Cu : Cg;
    const int* gather = g_elist + e * PN;

    int tid  = threadIdx.x;
    int lane = tid & 31;
    int w    = tid >> 5;
    int wm   = w >> 1;
    int wn   = w & 1;

    int a_r  = tid >> 2;
    int a_kq = (tid & 3) * 4;
    int b_k  = tid >> 5;
    int b_nq = (tid & 31) * 4;

    float4 aV[4], bV[4];
    float acc[2][8][4];
#pragma unroll
    for (int mf = 0; mf < 2; mf++)
#pragma unroll
        for (int nf = 0; nf < 8; nf++)
#pragma unroll
            for (int c = 0; c < 4; c++) acc[mf][nf][c] = 0.0f;

    auto loadA = [&](int k0) {
#pragma unroll
        for (int i = 0; i < 2; i++) {
            int pos = m0 + a_r + i * 64;
            if (pos < cnt) {
                int ar = gather[pos];
                const float* row = &A[(size_t)ar * K + k0 + a_kq];
                aV[i * 2 + 0] = *reinterpret_cast<const float4*>(row);
                aV[i * 2 + 1] = *reinterpret_cast<const float4*>(row + 16);
            } else {
                aV[i * 2 + 0] = make_float4(0.f, 0.f, 0.f, 0.f);
                aV[i * 2 + 1] = make_float4(0.f, 0.f, 0.f, 0.f);
            }
        }
    };
    auto loadB = [&](int k0) {
        int col = n0 + b_nq;
#pragma unroll
        for (int i = 0; i < 4; i++)
            bV[i] = *reinterpret_cast<const float4*>(&B[(size_t)(k0 + b_k + i * 8) * Nc + col]);
    };
    auto stsTile = [&](int buf) {
#pragma unroll
        for (int i = 0; i < 2; i++) {
            int r = a_r + i * 64;
#pragma unroll
            for (int j = 0; j < 2; j++) {
                float4 av = aV[i * 2 + j];
                uint4 at = make_uint4(f2tf32(av.x), f2tf32(av.y), f2tf32(av.z), f2tf32(av.w));
                *reinterpret_cast<uint4*>(&AS_(buf, r, a_kq + j * 16)) = at;
            }
        }
#pragma unroll
        for (int i = 0; i < 4; i++) {
            uint4 bt = make_uint4(f2tf32(bV[i].x), f2tf32(bV[i].y),
                                  f2tf32(bV[i].z), f2tf32(bV[i].w));
            *reinterpret_cast<uint4*>(&BS_(buf, b_k + i * 8, b_nq)) = bt;
        }
    };

    loadA(0); loadB(0);
    stsTile(0);
    __syncthreads();

    int buf = 0;
    for (int k0 = KT; k0 <= K; k0 += KT) {
        bool nxt = (k0 < K);
        if (nxt) { loadA(k0); loadB(k0); }
#pragma unroll
        for (int s = 0; s < 4; s++) {
            uint32_t afr[2][4], bfr[8][2];
            int kk = s * 8 + (lane & 3);
#pragma unroll
            for (int mf = 0; mf < 2; mf++) {
                int rb = wm * 32 + mf * 16 + (lane >> 2);
                afr[mf][0] = AS_(buf, rb, kk);
                afr[mf][1] = AS_(buf, rb + 8, kk);
                afr[mf][2] = AS_(buf, rb, kk + 4);
                afr[mf][3] = AS_(buf, rb + 8, kk + 4);
            }
#pragma unroll
            for (int nf = 0; nf < 8; nf++) {
                int cb = wn * 64 + nf * 8 + (lane >> 2);
                bfr[nf][0] = BS_(buf, kk, cb);
                bfr[nf][1] = BS_(buf, kk + 4, cb);
            }
#pragma unroll
            for (int mf = 0; mf < 2; mf++)
#pragma unroll
                for (int nf = 0; nf < 8; nf++)
                    mma_tf32(acc[mf][nf], afr[mf], bfr[nf]);
        }
        if (nxt) stsTile(buf ^ 1);
        __syncthreads();
        buf ^= 1;
    }

#pragma unroll
    for (int mf = 0; mf < 2; mf++) {
#pragma unroll
        for (int r2 = 0; r2 < 2; r2++) {
            int pos = m0 + wm * 32 + mf * 16 + (lane >> 2) + r2 * 8;
            if (pos >= cnt) continue;
            int crow = gather[pos];
#pragma unroll
            for (int nf = 0; nf < 8; nf++) {
#pragma unroll
                for (int c2 = 0; c2 < 2; c2++) {
                    int col = n0 + wn * 64 + nf * 8 + (lane & 3) * 2 + c2;
                    size_t ci = (size_t)crow * Nc + col;
                    float val = acc[mf][nf][r2 * 2 + c2];
                    if (residual) val += residual[ci];
                    C[ci] = val;
                }
            }
        }
    }
}

// ---------------- per-head RMSNorm + RoPE ----------------
__global__ void qknorm_rope_kernel(float* __restrict__ x, const float* __restrict__ w,
                                   int heads, int nrows) {
    int row = blockIdx.x * 8 + (threadIdx.x >> 5);
    if (row >= nrows) return;
    int lane = threadIdx.x & 31;
    int n = row / heads;
    float* base = x + (size_t)row * PDH;
    float x1 = base[lane];
    float x2 = base[lane + 32];
    float s = x1 * x1 + x2 * x2;
#pragma unroll
    for (int off = 16; off > 0; off >>= 1) s += __shfl_xor_sync(0xffffffffu, s, off);
    float scale = rsqrtf(s / (float)PDH + P_EPS);
    x1 *= scale * w[lane];
    x2 *= scale * w[lane + 32];
    float c  = g_cosT[n * 32 + lane];
    float sn = g_sinT[n * 32 + lane];
    base[lane]      = x1 * c - x2 * sn;
    base[lane + 32] = x2 * c + x1 * sn;
}

// ---------------- tensor-core flash attention ----------------
__global__ __launch_bounds__(256, 2)
void attn_tc_kernel(const float* __restrict__ q, const float* __restrict__ k,
                    const float* __restrict__ v, float* __restrict__ o) {
    __shared__ uint32_t Ks[32][68];
    __shared__ uint32_t Vs[32][72];
    __shared__ uint32_t Ps[128][36];

    int qb = blockIdx.x, h = blockIdx.y;
    int kvh = h >> 2;
    int q0 = qb * 128;
    int tid = threadIdx.x;
    int lane = tid & 31;
    int w = tid >> 5;
    int lr = lane >> 2, lc = lane & 3;

    uint32_t qfr[8][4];
    {
        const float* qb_ = q + (size_t)(q0 + w * 16) * PD + h * PDH;
#pragma unroll
        for (int ks = 0; ks < 8; ks++) {
            int c = ks * 8 + lc;
            qfr[ks][0] = f2tf32(qb_[(size_t)lr * PD + c]);
            qfr[ks][1] = f2tf32(qb_[(size_t)(lr + 8) * PD + c]);
            qfr[ks][2] = f2tf32(qb_[(size_t)lr * PD + c + 4]);
            qfr[ks][3] = f2tf32(qb_[(size_t)(lr + 8) * PD + c + 4]);
        }
    }

    float accO[8][4];
#pragma unroll
    for (int nf = 0; nf < 8; nf++)
#pragma unroll
        for (int c = 0; c < 4; c++) accO[nf][c] = 0.0f;
    float m0 = -INFINITY, m1 = -INFINITY, l0 = 0.0f, l1 = 0.0f;
    const float scale = 0.125f;

    for (int t = 0; t < PN / 32; t++) {
#pragma unroll
        for (int it = 0; it < 2; it++) {
            int i = tid + it * 256;
            int kv = i >> 4, d4 = (i & 15) * 4;
            size_t gi = (size_t)(t * 32 + kv) * (PKV * PDH) + kvh * PDH + d4;
            float4 kf = *reinterpret_cast<const float4*>(&k[gi]);
            float4 vf = *reinterpret_cast<const float4*>(&v[gi]);
            uint4 kt = make_uint4(f2tf32(kf.x), f2tf32(kf.y), f2tf32(kf.z), f2tf32(kf.w));
            uint4 vt = make_uint4(f2tf32(vf.x), f2tf32(vf.y), f2tf32(vf.z), f2tf32(vf.w));
            *reinterpret_cast<uint4*>(&Ks[kv][d4]) = kt;
            *reinterpret_cast<uint4*>(&Vs[kv][d4]) = vt;
        }
        __syncthreads();

        float sacc[4][4];
#pragma unroll
        for (int nf = 0; nf < 4; nf++)
#pragma unroll
            for (int c = 0; c < 4; c++) sacc[nf][c] = 0.0f;
#pragma unroll
        for (int ks = 0; ks < 8; ks++) {
#pragma unroll
            for (int nf = 0; nf < 4; nf++) {
                uint32_t b[2];
                b[0] = Ks[nf * 8 + lr][ks * 8 + lc];
                b[1] = Ks[nf * 8 + lr][ks * 8 + lc + 4];
                mma_tf32(sacc[nf], qfr[ks], b);
            }
        }

        float mloc0 = -INFINITY, mloc1 = -INFINITY;
#pragma unroll
        for (int nf = 0; nf < 4; nf++) {
#pragma unroll
            for (int c = 0; c < 4; c++) sacc[nf][c] *= scale;
            mloc0 = fmaxf(mloc0, fmaxf(sacc[nf][0], sacc[nf][1]));
            mloc1 = fmaxf(mloc1, fmaxf(sacc[nf][2], sacc[nf][3]));
        }
        mloc0 = fmaxf(mloc0, __shfl_xor_sync(0xffffffffu, mloc0, 1));
        mloc0 = fmaxf(mloc0, __shfl_xor_sync(0xffffffffu, mloc0, 2));
        mloc1 = fmaxf(mloc1, __shfl_xor_sync(0xffffffffu, mloc1, 1));
        mloc1 = fmaxf(mloc1, __shfl_xor_sync(0xffffffffu, mloc1, 2));
        float mn0 = fmaxf(m0, mloc0), mn1 = fmaxf(m1, mloc1);
        float corr0 = __expf(m0 - mn0), corr1 = __expf(m1 - mn1);
        float ls0 = 0.0f, ls1 = 0.0f;
        int prow = w * 16 + lr;
#pragma unroll
        for (int nf = 0; nf < 4; nf++) {
            float p00 = __expf(sacc[nf][0] - mn0);
            float p01 = __expf(sacc[nf][1] - mn0);
            float p10 = __expf(sacc[nf][2] - mn1);
            float p11 = __expf(sacc[nf][3] - mn1);
            ls0 += p00 + p01;
            ls1 += p10 + p11;
            int col = nf * 8 + 2 * lc;
            *reinterpret_cast<uint2*>(&Ps[prow][col])     = make_uint2(f2tf32(p00), f2tf32(p01));
            *reinterpret_cast<uint2*>(&Ps[prow + 8][col]) = make_uint2(f2tf32(p10), f2tf32(p11));
        }
        ls0 += __shfl_xor_sync(0xffffffffu, ls0, 1);
        ls0 += __shfl_xor_sync(0xffffffffu, ls0, 2);
        ls1 += __shfl_xor_sync(0xffffffffu, ls1, 1);
        ls1 += __shfl_xor_sync(0xffffffffu, ls1, 2);
        l0 = l0 * corr0 + ls0;
        l1 = l1 * corr1 + ls1;
        m0 = mn0; m1 = mn1;
#pragma unroll
        for (int nf = 0; nf < 8; nf++) {
            accO[nf][0] *= corr0; accO[nf][1] *= corr0;
            accO[nf][2] *= corr1; accO[nf][3] *= corr1;
        }
        __syncthreads();

#pragma unroll
        for (int ks2 = 0; ks2 < 4; ks2++) {
            uint32_t a[4];
            a[0] = Ps[w * 16 + lr][ks2 * 8 + lc];
            a[1] = Ps[w * 16 + lr + 8][ks2 * 8 + lc];
            a[2] = Ps[w * 16 + lr][ks2 * 8 + lc + 4];
            a[3] = Ps[w * 16 + lr + 8][ks2 * 8 + lc + 4];
#pragma unroll
            for (int nf = 0; nf < 8; nf++) {
                uint32_t b[2];
                b[0] = Vs[ks2 * 8 + lc][nf * 8 + lr];
                b[1] = Vs[ks2 * 8 + lc + 4][nf * 8 + lr];
                mma_tf32(accO[nf], a, b);
            }
        }
        __syncthreads();
    }

    float il0 = 1.0f / l0, il1 = 1.0f / l1;
    int row0 = q0 + w * 16 + lr;
#pragma unroll
    for (int nf = 0; nf < 8; nf++) {
        int col = h * PDH + nf * 8 + 2 * lc;
        *reinterpret_cast<float2*>(&o[(size_t)row0 * PD + col]) =
            make_float2(accO[nf][0] * il0, accO[nf][1] * il0);
        *reinterpret_cast<float2*>(&o[(size_t)(row0 + 8) * PD + col]) =
            make_float2(accO[nf][2] * il1, accO[nf][3] * il1);
    }
}

// ---------------- fused state-update ----------------
__global__ void fuse1_kernel(const float* __restrict__ co, const float* __restrict__ velocity,
                             const float* __restrict__ o, const float* __restrict__ mu_cur,
                             const float* __restrict__ hidden_in,
                             float* __restrict__ out_vnext, float* __restrict__ hidmid) {
    size_t i = (size_t)blockIdx.x * blockDim.x + threadIdx.x;
    if (i >= (size_t)PN * PD) return;
    int n = (int)(i / PD), d = (int)(i % PD);
    const float* cor = co + (size_t)n * 3 * PD;
    float alpha = sigmoidf_(cor[d]);
    float beta  = fminf(softplusf_(cor[PD + d]), 2.0f);
    float gate  = sigmoidf_(cor[2 * PD + d]);
    float ov = o[i], mc = mu_cur[i], vel = velocity[i];
    float err = ov - mc;
    float vn = alpha * vel - beta * err;
    vn = fminf(fmaxf(vn, -10.0f), 10.0f);
    out_vnext[i] = vn;
    hidmid[i] = hidden_in[i] + ov + P_DT * gate * vn;
}

// ---------------- router ----------------
__global__ void router_kernel(const float* __restrict__ mu_cur, const float* __restrict__ w,
                              const int* __restrict__ token_ids) {
    int tkn = blockIdx.x * 8 + (threadIdx.x >> 5);
    if (tkn >= PN) return;
    int lane = threadIdx.x & 31;
    float lg[PE];
#pragma unroll
    for (int e = 0; e < PE; e++) lg[e] = 0.0f;
    const float* xr = mu_cur + (size_t)tkn * PD;
    for (int d = lane; d < PD; d += 32) {
        float xv = xr[d];
        const float* wr = w + (size_t)d * PE;
#pragma unroll
        for (int e = 0; e < PE; e++) lg[e] += xv * wr[e];
    }
#pragma unroll
    for (int e = 0; e < PE; e++) {
#pragma unroll
        for (int off = 16; off > 0; off >>= 1)
            lg[e] += __shfl_xor_sync(0xffffffffu, lg[e], off);
    }
    if (lane == 0) {
        int b = token_ids[tkn] % PE;
        lg[b] += P_BASE_SCALE;
        int best = 0; float bv = lg[0];
#pragma unroll
        for (int e = 1; e < PE; e++) {
            if (lg[e] > bv) { bv = lg[e]; best = e; }
        }
        int slot = atomicAdd(&g_ecount[best], 1);
        g_elist[best * PN + slot] = tkn;
    }
}

__global__ void midcombine_kernel() {
    size_t i = (size_t)blockIdx.x * blockDim.x + threadIdx.x;
    if (i >= (size_t)PN * PF) return;
    float gv = g_G[i];
    g_mid[i] = (gv / (1.0f + expf(-gv))) * g_U[i];
}

// ---------------- host launch ----------------
static inline void* sym_addr(const void* sym) {
    void* p = nullptr;
    cudaGetSymbolAddress(&p, sym);
    return p;
}

extern "C" void kernel_launch(void* const* d_in, const int* in_sizes, int n_in,
                              void* d_out, int out_size) {
    const float* hidden    = (const float*)d_in[0];
    const int*   positions = (const int*)d_in[1];
    const float* velocity  = (const float*)d_in[2];
    const int*   token_ids = (const int*)d_in[3];
    const float* mu_prev   = (const float*)d_in[4];
    const float* ln1_w     = (const float*)d_in[5];
    const float* ln2_w     = (const float*)d_in[6];
    const float* wq        = (const float*)d_in[7];
    const float* wk        = (const float*)d_in[8];
    const float* wv        = (const float*)d_in[9];
    const float* wo        = (const float*)d_in[10];
    const float* w_mu_q    = (const float*)d_in[11];
    const float* w_mu_k    = (const float*)d_in[12];
    const float* w_mu_v    = (const float*)d_in[13];
    const float* qnorm_w   = (const float*)d_in[14];
    const float* knorm_w   = (const float*)d_in[15];
    const float* dyn_mu    = (const float*)d_in[16];
    const float* dyn_proj  = (const float*)d_in[17];
    const float* ctrl_in_w = (const float*)d_in[18];
    const float* ctrl_in_b = (const float*)d_in[19];
    const float* ctrl_out_w= (const float*)d_in[20];
    const float* ctrl_out_b= (const float*)d_in[21];
    const float* mu_router = (const float*)d_in[22];
    const float* w_gate    = (const float*)d_in[23];
    const float* w_up      = (const float*)d_in[24];
    const float* w_down    = (const float*)d_in[25];

    float* out_hidden = (float*)d_out;
    float* out_vnext  = out_hidden + (size_t)PN * PD;
    float* out_mucur  = out_vnext  + (size_t)PN * PD;

    float* p_hnorm  = (float*)sym_addr(g_hnorm);
    float* p_q      = (float*)sym_addr(g_q);
    float* p_k      = (float*)sym_addr(g_k);
    float* p_v      = (float*)sym_addr(g_v);
    float* p_attno  = (float*)sym_addr(g_attno);
    float* p_o      = (float*)sym_addr(g_o);
    float* p_ctrl   = (float*)sym_addr(g_ctrl);
    float* p_co     = (float*)sym_addr(g_co);
    float* p_hidmid = (float*)sym_addr(g_hidmid);
    float* p_xnorm  = (float*)sym_addr(g_xnorm);
    float* p_G      = (float*)sym_addr(g_G);
    float* p_U      = (float*)sym_addr(g_U);
    float* p_mid    = (float*)sym_addr(g_mid);

    // opt-in to >48KB dynamic smem (host-side attribute, not an allocation)
    static bool attr_done = false;
    if (!attr_done) {
        cudaFuncSetAttribute(tf32_gemm_multi,
                             cudaFuncAttributeMaxDynamicSharedMemorySize, GEMM_SMEM_BYTES);
        cudaFuncSetAttribute(moe_gemm_kernel,
                             cudaFuncAttributeMaxDynamicSharedMemorySize, GEMM_SMEM_BYTES);
        attr_done = true;
    }

    zero_counts_kernel<<<1, 32>>>();
    rope_table_kernel<<<(PN * 32 + 255) / 256, 256>>>(positions);
    rmsnorm_kernel<<<PN, 256>>>(hidden, ln1_w, p_hnorm);

    // QKV in ONE launch
    {
        GDesc dq { p_hnorm, mu_prev, wq, w_mu_q, nullptr, p_q, PH * PDH, 2 * PD, PD, 0 };
        GDesc dk { p_hnorm, mu_prev, wk, w_mu_k, nullptr, p_k, PKV * PDH, 2 * PD, PD, 0 };
        GDesc dv { p_hnorm, mu_prev, wv, w_mu_v, nullptr, p_v, PKV * PDH, 2 * PD, PD, 0 };
        tf32_gemm_multi<<<dim3(8, 16, 3), 256, GEMM_SMEM_BYTES>>>(dq, dk, dv);
    }

    qknorm_rope_kernel<<<(PN * PH + 7) / 8, 256>>>(p_q, qnorm_w, PH, PN * PH);
    qknorm_rope_kernel<<<(PN * PKV + 7) / 8, 256>>>(p_k, knorm_w, PKV, PN * PKV);

    attn_tc_kernel<<<dim3(PN / 128, PH), 256>>>(p_q, p_k, p_v, p_attno);

    // o = attno @ wo
    {
        GDesc d { p_attno, nullptr, wo, nullptr, nullptr, p_o, PD, PD, PD, 0 };
        tf32_gemm_multi<<<dim3(8, 16, 1), 256, GEMM_SMEM_BYTES>>>(d, d, d);
    }

    // dyn-proj and ctrl concurrently
    {
        GDesc dd { p_o, nullptr, dyn_proj, nullptr, dyn_mu, out_mucur, PD, PD, PD, 0 };
        GDesc dc { p_o, velocity, ctrl_in_w, ctrl_in_w + PD * PCH, ctrl_in_b, p_ctrl,
                   PCH, 2 * PD, PD, 2 };
        tf32_gemm_multi<<<dim3(8, 16, 2), 256, GEMM_SMEM_BYTES>>>(dd, dc, dc);
    }

    // co = ctrl @ ctrl_out_w + ctrl_out_b
    {
        GDesc d { p_ctrl, nullptr, ctrl_out_w, nullptr, ctrl_out_b, p_co, 3 * PD, PCH, PCH, 0 };
        tf32_gemm_multi<<<dim3(24, 16, 1), 256, GEMM_SMEM_BYTES>>>(d, d, d);
    }

    fuse1_kernel<<<(PN * PD + 255) / 256, 256>>>(p_co, velocity, p_o, out_mucur, hidden,
                                                 out_vnext, p_hidmid);

    rmsnorm_kernel<<<PN, 256>>>(p_hidmid, ln2_w, p_xnorm);
    router_kernel<<<(PN + 7) / 8, 256>>>(out_mucur, mu_router, token_ids);

    moe_gemm_kernel<<<dim3(32, 16, PE), 256, GEMM_SMEM_BYTES>>>(p_xnorm, w_gate, w_up,
                                               (size_t)PD * PF, p_G, p_U,
                                               nullptr, PF, PD, 16);
    midcombine_kernel<<<(PN * PF + 255) / 256, 256>>>();

    moe_gemm_kernel<<<dim3(8, 16, PE), 256, GEMM_SMEM_BYTES>>>(p_mid, w_down, nullptr,
                                              (size_t)PF * PD, out_hidden, nullptr,
                                              p_hidmid, PD, PF, 8);
}

// round 15
// speedup vs baseline: 1.1473x; 1.0017x over previous
#include <cuda_runtime.h>
#include <math.h>
#include <stdint.h>

// ---------------- problem constants ----------------
#define PN   2048
#define PD   1024
#define PH   16
#define PKV  4
#define PDH  64
#define PE   8
#define PF   2048
#define PCH  64
#define P_EPS 1e-6f
#define P_DT  0.1f
#define P_BASE_SCALE 10.0f

// GEMM k-tile and smem geometry (dynamic smem)
#define KT      32
#define ASTR    36
#define BSTR    136
#define ASZ     (128 * ASTR)
#define BSZ     (KT * BSTR)
#define GEMM_SMEM_BYTES ((2 * ASZ + 2 * BSZ) * 4)   // 71680 B

// ---------------- scratch ----------------
__device__ float g_hnorm[PN * PD];
__device__ float g_q[PN * PH * PDH];
__device__ float g_k[PN * PKV * PDH];
__device__ float g_v[PN * PKV * PDH];
__device__ float g_attno[PN * PD];
__device__ float g_o[PN * PD];
__device__ float g_ctrl[PN * PCH];
__device__ float g_co[PN * 3 * PD];
__device__ float g_hidmid[PN * PD];
__device__ float g_xnorm[PN * PD];
__device__ float g_G[PN * PF];
__device__ float g_U[PN * PF];
__device__ float g_mid[PN * PF];
__device__ float g_cosT[PN * 32];
__device__ float g_sinT[PN * 32];
__device__ int   g_elist[PE * PN];
__device__ int   g_ecount[PE];

// ---------------- helpers ----------------
__device__ __forceinline__ float sigmoidf_(float x) { return 1.0f / (1.0f + expf(-x)); }
__device__ __forceinline__ float softplusf_(float x) {
    return fmaxf(x, 0.0f) + log1pf(expf(-fabsf(x)));
}
__device__ __forceinline__ uint32_t f2tf32(float f) {
    uint32_t r; asm("cvt.rna.tf32.f32 %0, %1;" : "=r"(r) : "f"(f)); return r;
}
__device__ __forceinline__ void mma_tf32(float* d, const uint32_t* a, const uint32_t* b) {
    asm volatile(
        "mma.sync.aligned.m16n8k8.row.col.f32.tf32.tf32.f32 "
        "{%0,%1,%2,%3}, {%4,%5,%6,%7}, {%8,%9}, {%0,%1,%2,%3};"
        : "+f"(d[0]), "+f"(d[1]), "+f"(d[2]), "+f"(d[3])
        : "r"(a[0]), "r"(a[1]), "r"(a[2]), "r"(a[3]), "r"(b[0]), "r"(b[1]));
}

__global__ void zero_counts_kernel() {
    int t = threadIdx.x;
    if (t < PE) g_ecount[t] = 0;
}

__global__ void rope_table_kernel(const int* __restrict__ positions) {
    __shared__ float sm_inv[32];
    if (threadIdx.x < 32) {
        double inv = pow(10000.0, -((double)(2 * threadIdx.x)) / 64.0);
        sm_inv[threadIdx.x] = (float)inv;
    }
    __syncthreads();
    int i = blockIdx.x * 256 + threadIdx.x;
    if (i >= PN * 32) return;
    int n = i >> 5, f = i & 31;
    float ang = (float)positions[n] * sm_inv[f];
    float s, c;
    sincosf(ang, &s, &c);
    g_cosT[i] = c;
    g_sinT[i] = s;
}

__global__ void rmsnorm_kernel(const float* __restrict__ x, const float* __restrict__ w,
                               float* __restrict__ out) {
    int row = blockIdx.x;
    int tid = threadIdx.x;
    __shared__ float red[256];
    const float* xr = x + (size_t)row * PD;
    float s = 0.0f;
    for (int d = tid; d < PD; d += 256) { float v = xr[d]; s += v * v; }
    red[tid] = s; __syncthreads();
    for (int off = 128; off > 0; off >>= 1) {
        if (tid < off) red[tid] += red[tid + off];
        __syncthreads();
    }
    float scale = rsqrtf(red[0] / (float)PD + P_EPS);
    float* orow = out + (size_t)row * PD;
    for (int d = tid; d < PD; d += 256) orow[d] = xr[d] * scale * w[d];
}

// ---------------- multi-descriptor TF32 GEMM, k-tile=32, dynamic smem ----------------
struct GDesc {
    const float* A; const float* A2;
    const float* B; const float* B2;
    const float* bias;
    float* C;
    int Nc; int K; int K1; int flags;    // flags bit1: SiLU
};

__global__ __launch_bounds__(256, 2)
void tf32_gemm_multi(GDesc d0, GDesc d1, GDesc d2) {
    extern __shared__ uint32_t sm[];
    uint32_t* Asm = sm;                    // [2][128][ASTR]
    uint32_t* Bsm = sm + 2 * ASZ;          // [2][KT][BSTR]
#define AS_(b, r, k) Asm[(b) * ASZ + (r) * ASTR + (k)]
#define BS_(b, r, n) Bsm[(b) * BSZ + (r) * BSTR + (n)]

    GDesc d = (blockIdx.z == 0) ? d0 : ((blockIdx.z == 1) ? d1 : d2);
    int m0 = blockIdx.y * 128;
    int n0 = blockIdx.x * 128;
    if (n0 >= d.Nc) return;

    int tid  = threadIdx.x;
    int lane = tid & 31;
    int w    = tid >> 5;
    int wm   = w >> 1;
    int wn   = w & 1;

    int a_r  = tid >> 2;
    int a_kq = (tid & 3) * 4;
    int b_k  = tid >> 5;
    int b_nq = (tid & 31) * 4;

    float4 aV[4], bV[4];
    float acc[2][8][4];
#pragma unroll
    for (int mf = 0; mf < 2; mf++)
#pragma unroll
        for (int nf = 0; nf < 8; nf++)
#pragma unroll
            for (int c = 0; c < 4; c++) acc[mf][nf][c] = 0.0f;

    auto loadA = [&](int k0) {
        const float* Ap = d.A; int lda = d.K1; int kk = k0;
        if (k0 >= d.K1) { Ap = d.A2; lda = d.K - d.K1; kk = k0 - d.K1; }
#pragma unroll
        for (int i = 0; i < 2; i++) {
            int pos = m0 + a_r + i * 64;
            const float* row = &Ap[(size_t)pos * lda + kk + a_kq];
            aV[i * 2 + 0] = *reinterpret_cast<const float4*>(row);
            aV[i * 2 + 1] = *reinterpret_cast<const float4*>(row + 16);
        }
    };
    auto loadB = [&](int k0) {
        const float* Bp = d.B; int kk = k0;
        if (k0 >= d.K1) { Bp = d.B2; kk = k0 - d.K1; }
        int col = n0 + b_nq;
#pragma unroll
        for (int i = 0; i < 4; i++) {
            if (col < d.Nc) {
                bV[i] = *reinterpret_cast<const float4*>(&Bp[(size_t)(kk + b_k + i * 8) * d.Nc + col]);
            } else {
                bV[i] = make_float4(0.f, 0.f, 0.f, 0.f);
            }
        }
    };
    auto stsTile = [&](int buf) {
#pragma unroll
        for (int i = 0; i < 2; i++) {
            int r = a_r + i * 64;
#pragma unroll
            for (int j = 0; j < 2; j++) {
                float4 av = aV[i * 2 + j];
                uint4 at = make_uint4(f2tf32(av.x), f2tf32(av.y), f2tf32(av.z), f2tf32(av.w));
                *reinterpret_cast<uint4*>(&AS_(buf, r, a_kq + j * 16)) = at;
            }
        }
#pragma unroll
        for (int i = 0; i < 4; i++) {
            uint4 bt = make_uint4(f2tf32(bV[i].x), f2tf32(bV[i].y),
                                  f2tf32(bV[i].z), f2tf32(bV[i].w));
            *reinterpret_cast<uint4*>(&BS_(buf, b_k + i * 8, b_nq)) = bt;
        }
    };

    loadA(0); loadB(0);
    stsTile(0);
    __syncthreads();

    int buf = 0;
    for (int k0 = KT; k0 <= d.K; k0 += KT) {
        bool nxt = (k0 < d.K);
        if (nxt) { loadA(k0); loadB(k0); }
#pragma unroll
        for (int s = 0; s < 4; s++) {
            uint32_t afr[2][4], bfr[8][2];
            int kk = s * 8 + (lane & 3);
#pragma unroll
            for (int mf = 0; mf < 2; mf++) {
                int rb = wm * 32 + mf * 16 + (lane >> 2);
                afr[mf][0] = AS_(buf, rb, kk);
                afr[mf][1] = AS_(buf, rb + 8, kk);
                afr[mf][2] = AS_(buf, rb, kk + 4);
                afr[mf][3] = AS_(buf, rb + 8, kk + 4);
            }
#pragma unroll
            for (int nf = 0; nf < 8; nf++) {
                int cb = wn * 64 + nf * 8 + (lane >> 2);
                bfr[nf][0] = BS_(buf, kk, cb);
                bfr[nf][1] = BS_(buf, kk + 4, cb);
            }
#pragma unroll
            for (int mf = 0; mf < 2; mf++)
#pragma unroll
                for (int nf = 0; nf < 8; nf++)
                    mma_tf32(acc[mf][nf], afr[mf], bfr[nf]);
        }
        if (nxt) stsTile(buf ^ 1);
        __syncthreads();
        buf ^= 1;
    }

#pragma unroll
    for (int mf = 0; mf < 2; mf++) {
#pragma unroll
        for (int r2 = 0; r2 < 2; r2++) {
            int crow = m0 + wm * 32 + mf * 16 + (lane >> 2) + r2 * 8;
#pragma unroll
            for (int nf = 0; nf < 8; nf++) {
#pragma unroll
                for (int c2 = 0; c2 < 2; c2++) {
                    int col = n0 + wn * 64 + nf * 8 + (lane & 3) * 2 + c2;
                    if (col >= d.Nc) continue;
                    size_t ci = (size_t)crow * d.Nc + col;
                    float val = acc[mf][nf][r2 * 2 + c2];
                    if (d.bias) val += d.bias[col];
                    if (d.flags & 2) val = val / (1.0f + expf(-val));
                    d.C[ci] = val;
                }
            }
        }
    }
}

// ---------------- MoE GEMM: grid.z = expert, gate/up split along x, k-tile=32 ----------------
__global__ __launch_bounds__(256, 2)
void moe_gemm_kernel(const float* __restrict__ A,
                     const float* __restrict__ Bg, const float* __restrict__ Bu,
                     size_t bStride, float* __restrict__ Cg, float* __restrict__ Cu,
                     const float* __restrict__ residual,
                     int Nc, int K, int xPart) {
    extern __shared__ uint32_t sm[];
    uint32_t* Asm = sm;
    uint32_t* Bsm = sm + 2 * ASZ;

    int e = blockIdx.z;
    int cnt = g_ecount[e];
    int m0 = blockIdx.y * 128;
    if (m0 >= cnt) return;
    int part = blockIdx.x / xPart;
    int n0 = (blockIdx.x % xPart) * 128;
    const float* B = (part ? Bu : Bg) + (size_t)e * bStride;
    float* C = part ? Cu : Cg;
    const int* gather = g_elist + e * PN;

    int tid  = threadIdx.x;
    int lane = tid & 31;
    int w    = tid >> 5;
    int wm   = w >> 1;
    int wn   = w & 1;

    int a_r  = tid >> 2;
    int a_kq = (tid & 3) * 4;
    int b_k  = tid >> 5;
    int b_nq = (tid & 31) * 4;

    float4 aV[4], bV[4];
    float acc[2][8][4];
#pragma unroll
    for (int mf = 0; mf < 2; mf++)
#pragma unroll
        for (int nf = 0; nf < 8; nf++)
#pragma unroll
            for (int c = 0; c < 4; c++) acc[mf][nf][c] = 0.0f;

    auto loadA = [&](int k0) {
#pragma unroll
        for (int i = 0; i < 2; i++) {
            int pos = m0 + a_r + i * 64;
            if (pos < cnt) {
                int ar = gather[pos];
                const float* row = &A[(size_t)ar * K + k0 + a_kq];
                aV[i * 2 + 0] = *reinterpret_cast<const float4*>(row);
                aV[i * 2 + 1] = *reinterpret_cast<const float4*>(row + 16);
            } else {
                aV[i * 2 + 0] = make_float4(0.f, 0.f, 0.f, 0.f);
                aV[i * 2 + 1] = make_float4(0.f, 0.f, 0.f, 0.f);
            }
        }
    };
    auto loadB = [&](int k0) {
        int col = n0 + b_nq;
#pragma unroll
        for (int i = 0; i < 4; i++)
            bV[i] = *reinterpret_cast<const float4*>(&B[(size_t)(k0 + b_k + i * 8) * Nc + col]);
    };
    auto stsTile = [&](int buf) {
#pragma unroll
        for (int i = 0; i < 2; i++) {
            int r = a_r + i * 64;
#pragma unroll
            for (int j = 0; j < 2; j++) {
                float4 av = aV[i * 2 + j];
                uint4 at = make_uint4(f2tf32(av.x), f2tf32(av.y), f2tf32(av.z), f2tf32(av.w));
                *reinterpret_cast<uint4*>(&AS_(buf, r, a_kq + j * 16)) = at;
            }
        }
#pragma unroll
        for (int i = 0; i < 4; i++) {
            uint4 bt = make_uint4(f2tf32(bV[i].x), f2tf32(bV[i].y),
                                  f2tf32(bV[i].z), f2tf32(bV[i].w));
            *reinterpret_cast<uint4*>(&BS_(buf, b_k + i * 8, b_nq)) = bt;
        }
    };

    loadA(0); loadB(0);
    stsTile(0);
    __syncthreads();

    int buf = 0;
    for (int k0 = KT; k0 <= K; k0 += KT) {
        bool nxt = (k0 < K);
        if (nxt) { loadA(k0); loadB(k0); }
#pragma unroll
        for (int s = 0; s < 4; s++) {
            uint32_t afr[2][4], bfr[8][2];
            int kk = s * 8 + (lane & 3);
#pragma unroll
            for (int mf = 0; mf < 2; mf++) {
                int rb = wm * 32 + mf * 16 + (lane >> 2);
                afr[mf][0] = AS_(buf, rb, kk);
                afr[mf][1] = AS_(buf, rb + 8, kk);
                afr[mf][2] = AS_(buf, rb, kk + 4);
                afr[mf][3] = AS_(buf, rb + 8, kk + 4);
            }
#pragma unroll
            for (int nf = 0; nf < 8; nf++) {
                int cb = wn * 64 + nf * 8 + (lane >> 2);
                bfr[nf][0] = BS_(buf, kk, cb);
                bfr[nf][1] = BS_(buf, kk + 4, cb);
            }
#pragma unroll
            for (int mf = 0; mf < 2; mf++)
#pragma unroll
                for (int nf = 0; nf < 8; nf++)
                    mma_tf32(acc[mf][nf], afr[mf], bfr[nf]);
        }
        if (nxt) stsTile(buf ^ 1);
        __syncthreads();
        buf ^= 1;
    }

#pragma unroll
    for (int mf = 0; mf < 2; mf++) {
#pragma unroll
        for (int r2 = 0; r2 < 2; r2++) {
            int pos = m0 + wm * 32 + mf * 16 + (lane >> 2) + r2 * 8;
            if (pos >= cnt) continue;
            int crow = gather[pos];
#pragma unroll
            for (int nf = 0; nf < 8; nf++) {
#pragma unroll
                for (int c2 = 0; c2 < 2; c2++) {
                    int col = n0 + wn * 64 + nf * 8 + (lane & 3) * 2 + c2;
                    size_t ci = (size_t)crow * Nc + col;
                    float val = acc[mf][nf][r2 * 2 + c2];
                    if (residual) val += residual[ci];
                    C[ci] = val;
                }
            }
        }
    }
}

// ---------------- per-head RMSNorm + RoPE ----------------
__global__ void qknorm_rope_kernel(float* __restrict__ x, const float* __restrict__ w,
                                   int heads, int nrows) {
    int row = blockIdx.x * 8 + (threadIdx.x >> 5);
    if (row >= nrows) return;
    int lane = threadIdx.x & 31;
    int n = row / heads;
    float* base = x + (size_t)row * PDH;
    float x1 = base[lane];
    float x2 = base[lane + 32];
    float s = x1 * x1 + x2 * x2;
#pragma unroll
    for (int off = 16; off > 0; off >>= 1) s += __shfl_xor_sync(0xffffffffu, s, off);
    float scale = rsqrtf(s / (float)PDH + P_EPS);
    x1 *= scale * w[lane];
    x2 *= scale * w[lane + 32];
    float c  = g_cosT[n * 32 + lane];
    float sn = g_sinT[n * 32 + lane];
    base[lane]      = x1 * c - x2 * sn;
    base[lane + 32] = x2 * c + x1 * sn;
}

// ---------------- tensor-core flash attention ----------------
__global__ __launch_bounds__(256, 2)
void attn_tc_kernel(const float* __restrict__ q, const float* __restrict__ k,
                    const float* __restrict__ v, float* __restrict__ o) {
    __shared__ uint32_t Ks[32][68];
    __shared__ uint32_t Vs[32][72];
    __shared__ uint32_t Ps[128][36];

    int qb = blockIdx.x, h = blockIdx.y;
    int kvh = h >> 2;
    int q0 = qb * 128;
    int tid = threadIdx.x;
    int lane = tid & 31;
    int w = tid >> 5;
    int lr = lane >> 2, lc = lane & 3;

    uint32_t qfr[8][4];
    {
        const float* qb_ = q + (size_t)(q0 + w * 16) * PD + h * PDH;
#pragma unroll
        for (int ks = 0; ks < 8; ks++) {
            int c = ks * 8 + lc;
            qfr[ks][0] = f2tf32(qb_[(size_t)lr * PD + c]);
            qfr[ks][1] = f2tf32(qb_[(size_t)(lr + 8) * PD + c]);
            qfr[ks][2] = f2tf32(qb_[(size_t)lr * PD + c + 4]);
            qfr[ks][3] = f2tf32(qb_[(size_t)(lr + 8) * PD + c + 4]);
        }
    }

    float accO[8][4];
#pragma unroll
    for (int nf = 0; nf < 8; nf++)
#pragma unroll
        for (int c = 0; c < 4; c++) accO[nf][c] = 0.0f;
    float m0 = -INFINITY, m1 = -INFINITY, l0 = 0.0f, l1 = 0.0f;
    const float scale = 0.125f;

    for (int t = 0; t < PN / 32; t++) {
#pragma unroll
        for (int it = 0; it < 2; it++) {
            int i = tid + it * 256;
            int kv = i >> 4, d4 = (i & 15) * 4;
            size_t gi = (size_t)(t * 32 + kv) * (PKV * PDH) + kvh * PDH + d4;
            float4 kf = *reinterpret_cast<const float4*>(&k[gi]);
            float4 vf = *reinterpret_cast<const float4*>(&v[gi]);
            uint4 kt = make_uint4(f2tf32(kf.x), f2tf32(kf.y), f2tf32(kf.z), f2tf32(kf.w));
            uint4 vt = make_uint4(f2tf32(vf.x), f2tf32(vf.y), f2tf32(vf.z), f2tf32(vf.w));
            *reinterpret_cast<uint4*>(&Ks[kv][d4]) = kt;
            *reinterpret_cast<uint4*>(&Vs[kv][d4]) = vt;
        }
        __syncthreads();

        float sacc[4][4];
#pragma unroll
        for (int nf = 0; nf < 4; nf++)
#pragma unroll
            for (int c = 0; c < 4; c++) sacc[nf][c] = 0.0f;
#pragma unroll
        for (int ks = 0; ks < 8; ks++) {
#pragma unroll
            for (int nf = 0; nf < 4; nf++) {
                uint32_t b[2];
                b[0] = Ks[nf * 8 + lr][ks * 8 + lc];
                b[1] = Ks[nf * 8 + lr][ks * 8 + lc + 4];
                mma_tf32(sacc[nf], qfr[ks], b);
            }
        }

        float mloc0 = -INFINITY, mloc1 = -INFINITY;
#pragma unroll
        for (int nf = 0; nf < 4; nf++) {
#pragma unroll
            for (int c = 0; c < 4; c++) sacc[nf][c] *= scale;
            mloc0 = fmaxf(mloc0, fmaxf(sacc[nf][0], sacc[nf][1]));
            mloc1 = fmaxf(mloc1, fmaxf(sacc[nf][2], sacc[nf][3]));
        }
        mloc0 = fmaxf(mloc0, __shfl_xor_sync(0xffffffffu, mloc0, 1));
        mloc0 = fmaxf(mloc0, __shfl_xor_sync(0xffffffffu, mloc0, 2));
        mloc1 = fmaxf(mloc1, __shfl_xor_sync(0xffffffffu, mloc1, 1));
        mloc1 = fmaxf(mloc1, __shfl_xor_sync(0xffffffffu, mloc1, 2));
        float mn0 = fmaxf(m0, mloc0), mn1 = fmaxf(m1, mloc1);
        float corr0 = __expf(m0 - mn0), corr1 = __expf(m1 - mn1);
        float ls0 = 0.0f, ls1 = 0.0f;
        int prow = w * 16 + lr;
#pragma unroll
        for (int nf = 0; nf < 4; nf++) {
            float p00 = __expf(sacc[nf][0] - mn0);
            float p01 = __expf(sacc[nf][1] - mn0);
            float p10 = __expf(sacc[nf][2] - mn1);
            float p11 = __expf(sacc[nf][3] - mn1);
            ls0 += p00 + p01;
            ls1 += p10 + p11;
            int col = nf * 8 + 2 * lc;
            *reinterpret_cast<uint2*>(&Ps[prow][col])     = make_uint2(f2tf32(p00), f2tf32(p01));
            *reinterpret_cast<uint2*>(&Ps[prow + 8][col]) = make_uint2(f2tf32(p10), f2tf32(p11));
        }
        ls0 += __shfl_xor_sync(0xffffffffu, ls0, 1);
        ls0 += __shfl_xor_sync(0xffffffffu, ls0, 2);
        ls1 += __shfl_xor_sync(0xffffffffu, ls1, 1);
        ls1 += __shfl_xor_sync(0xffffffffu, ls1, 2);
        l0 = l0 * corr0 + ls0;
        l1 = l1 * corr1 + ls1;
        m0 = mn0; m1 = mn1;
#pragma unroll
        for (int nf = 0; nf < 8; nf++) {
            accO[nf][0] *= corr0; accO[nf][1] *= corr0;
            accO[nf][2] *= corr1; accO[nf][3] *= corr1;
        }
        __syncthreads();

#pragma unroll
        for (int ks2 = 0; ks2 < 4; ks2++) {
            uint32_t a[4];
            a[0] = Ps[w * 16 + lr][ks2 * 8 + lc];
            a[1] = Ps[w * 16 + lr + 8][ks2 * 8 + lc];
            a[2] = Ps[w * 16 + lr][ks2 * 8 + lc + 4];
            a[3] = Ps[w * 16 + lr + 8][ks2 * 8 + lc + 4];
#pragma unroll
            for (int nf = 0; nf < 8; nf++) {
                uint32_t b[2];
                b[0] = Vs[ks2 * 8 + lc][nf * 8 + lr];
                b[1] = Vs[ks2 * 8 + lc + 4][nf * 8 + lr];
                mma_tf32(accO[nf], a, b);
            }
        }
        __syncthreads();
    }

    float il0 = 1.0f / l0, il1 = 1.0f / l1;
    int row0 = q0 + w * 16 + lr;
#pragma unroll
    for (int nf = 0; nf < 8; nf++) {
        int col = h * PDH + nf * 8 + 2 * lc;
        *reinterpret_cast<float2*>(&o[(size_t)row0 * PD + col]) =
            make_float2(accO[nf][0] * il0, accO[nf][1] * il0);
        *reinterpret_cast<float2*>(&o[(size_t)(row0 + 8) * PD + col]) =
            make_float2(accO[nf][2] * il1, accO[nf][3] * il1);
    }
}

// ---------------- fused state-update + rmsnorm(ln2): one block per row ----------------
__global__ void fuse1_rms_kernel(const float* __restrict__ co, const float* __restrict__ velocity,
                                 const float* __restrict__ o, const float* __restrict__ mu_cur,
                                 const float* __restrict__ hidden_in, const float* __restrict__ ln2_w,
                                 float* __restrict__ out_vnext, float* __restrict__ hidmid,
                                 float* __restrict__ xnorm) {
    int n = blockIdx.x;
    int tid = threadIdx.x;
    __shared__ float red[256];
    const float* cor = co + (size_t)n * 3 * PD;
    size_t rowo = (size_t)n * PD;

    float hv[4];
    float loc = 0.0f;
#pragma unroll
    for (int j = 0; j < 4; j++) {
        int d = tid + j * 256;
        float alpha = sigmoidf_(cor[d]);
        float beta  = fminf(softplusf_(cor[PD + d]), 2.0f);
        float gate  = sigmoidf_(cor[2 * PD + d]);
        float ov = o[rowo + d], mc = mu_cur[rowo + d], vel = velocity[rowo + d];
        float err = ov - mc;
        float vn = alpha * vel - beta * err;
        vn = fminf(fmaxf(vn, -10.0f), 10.0f);
        out_vnext[rowo + d] = vn;
        float h = hidden_in[rowo + d] + ov + P_DT * gate * vn;
        hv[j] = h;
        loc += h * h;
    }
    red[tid] = loc; __syncthreads();
    for (int off = 128; off > 0; off >>= 1) {
        if (tid < off) red[tid] += red[tid + off];
        __syncthreads();
    }
    float scale = rsqrtf(red[0] / (float)PD + P_EPS);
#pragma unroll
    for (int j = 0; j < 4; j++) {
        int d = tid + j * 256;
        hidmid[rowo + d] = hv[j];
        xnorm[rowo + d] = hv[j] * scale * ln2_w[d];
    }
}

// ---------------- router ----------------
__global__ void router_kernel(const float* __restrict__ mu_cur, const float* __restrict__ w,
                              const int* __restrict__ token_ids) {
    int tkn = blockIdx.x * 8 + (threadIdx.x >> 5);
    if (tkn >= PN) return;
    int lane = threadIdx.x & 31;
    float lg[PE];
#pragma unroll
    for (int e = 0; e < PE; e++) lg[e] = 0.0f;
    const float* xr = mu_cur + (size_t)tkn * PD;
    for (int d = lane; d < PD; d += 32) {
        float xv = xr[d];
        const float* wr = w + (size_t)d * PE;
#pragma unroll
        for (int e = 0; e < PE; e++) lg[e] += xv * wr[e];
    }
#pragma unroll
    for (int e = 0; e < PE; e++) {
#pragma unroll
        for (int off = 16; off > 0; off >>= 1)
            lg[e] += __shfl_xor_sync(0xffffffffu, lg[e], off);
    }
    if (lane == 0) {
        int b = token_ids[tkn] % PE;
        lg[b] += P_BASE_SCALE;
        int best = 0; float bv = lg[0];
#pragma unroll
        for (int e = 1; e < PE; e++) {
            if (lg[e] > bv) { bv = lg[e]; best = e; }
        }
        int slot = atomicAdd(&g_ecount[best], 1);
        g_elist[best * PN + slot] = tkn;
    }
}

__global__ void midcombine_kernel() {
    size_t i = (size_t)blockIdx.x * blockDim.x + threadIdx.x;
    if (i >= (size_t)PN * PF) return;
    float gv = g_G[i];
    g_mid[i] = (gv / (1.0f + expf(-gv))) * g_U[i];
}

// ---------------- host launch ----------------
static inline void* sym_addr(const void* sym) {
    void* p = nullptr;
    cudaGetSymbolAddress(&p, sym);
    return p;
}

extern "C" void kernel_launch(void* const* d_in, const int* in_sizes, int n_in,
                              void* d_out, int out_size) {
    const float* hidden    = (const float*)d_in[0];
    const int*   positions = (const int*)d_in[1];
    const float* velocity  = (const float*)d_in[2];
    const int*   token_ids = (const int*)d_in[3];
    const float* mu_prev   = (const float*)d_in[4];
    const float* ln1_w     = (const float*)d_in[5];
    const float* ln2_w     = (const float*)d_in[6];
    const float* wq        = (const float*)d_in[7];
    const float* wk        = (const float*)d_in[8];
    const float* wv        = (const float*)d_in[9];
    const float* wo        = (const float*)d_in[10];
    const float* w_mu_q    = (const float*)d_in[11];
    const float* w_mu_k    = (const float*)d_in[12];
    const float* w_mu_v    = (const float*)d_in[13];
    const float* qnorm_w   = (const float*)d_in[14];
    const float* knorm_w   = (const float*)d_in[15];
    const float* dyn_mu    = (const float*)d_in[16];
    const float* dyn_proj  = (const float*)d_in[17];
    const float* ctrl_in_w = (const float*)d_in[18];
    const float* ctrl_in_b = (const float*)d_in[19];
    const float* ctrl_out_w= (const float*)d_in[20];
    const float* ctrl_out_b= (const float*)d_in[21];
    const float* mu_router = (const float*)d_in[22];
    const float* w_gate    = (const float*)d_in[23];
    const float* w_up      = (const float*)d_in[24];
    const float* w_down    = (const float*)d_in[25];

    float* out_hidden = (float*)d_out;
    float* out_vnext  = out_hidden + (size_t)PN * PD;
    float* out_mucur  = out_vnext  + (size_t)PN * PD;

    float* p_hnorm  = (float*)sym_addr(g_hnorm);
    float* p_q      = (float*)sym_addr(g_q);
    float* p_k      = (float*)sym_addr(g_k);
    float* p_v      = (float*)sym_addr(g_v);
    float* p_attno  = (float*)sym_addr(g_attno);
    float* p_o      = (float*)sym_addr(g_o);
    float* p_ctrl   = (float*)sym_addr(g_ctrl);
    float* p_co     = (float*)sym_addr(g_co);
    float* p_hidmid = (float*)sym_addr(g_hidmid);
    float* p_xnorm  = (float*)sym_addr(g_xnorm);
    float* p_G      = (float*)sym_addr(g_G);
    float* p_U      = (float*)sym_addr(g_U);
    float* p_mid    = (float*)sym_addr(g_mid);

    // opt-in to >48KB dynamic smem (host-side attribute, not an allocation)
    static bool attr_done = false;
    if (!attr_done) {
        cudaFuncSetAttribute(tf32_gemm_multi,
                             cudaFuncAttributeMaxDynamicSharedMemorySize, GEMM_SMEM_BYTES);
        cudaFuncSetAttribute(moe_gemm_kernel,
                             cudaFuncAttributeMaxDynamicSharedMemorySize, GEMM_SMEM_BYTES);
        attr_done = true;
    }

    zero_counts_kernel<<<1, 32>>>();
    rope_table_kernel<<<(PN * 32 + 255) / 256, 256>>>(positions);
    rmsnorm_kernel<<<PN, 256>>>(hidden, ln1_w, p_hnorm);

    // QKV in ONE launch
    {
        GDesc dq { p_hnorm, mu_prev, wq, w_mu_q, nullptr, p_q, PH * PDH, 2 * PD, PD, 0 };
        GDesc dk { p_hnorm, mu_prev, wk, w_mu_k, nullptr, p_k, PKV * PDH, 2 * PD, PD, 0 };
        GDesc dv { p_hnorm, mu_prev, wv, w_mu_v, nullptr, p_v, PKV * PDH, 2 * PD, PD, 0 };
        tf32_gemm_multi<<<dim3(8, 16, 3), 256, GEMM_SMEM_BYTES>>>(dq, dk, dv);
    }

    qknorm_rope_kernel<<<(PN * PH + 7) / 8, 256>>>(p_q, qnorm_w, PH, PN * PH);
    qknorm_rope_kernel<<<(PN * PKV + 7) / 8, 256>>>(p_k, knorm_w, PKV, PN * PKV);

    attn_tc_kernel<<<dim3(PN / 128, PH), 256>>>(p_q, p_k, p_v, p_attno);

    // o = attno @ wo
    {
        GDesc d { p_attno, nullptr, wo, nullptr, nullptr, p_o, PD, PD, PD, 0 };
        tf32_gemm_multi<<<dim3(8, 16, 1), 256, GEMM_SMEM_BYTES>>>(d, d, d);
    }

    // dyn-proj and ctrl concurrently
    {
        GDesc dd { p_o, nullptr, dyn_proj, nullptr, dyn_mu, out_mucur, PD, PD, PD, 0 };
        GDesc dc { p_o, velocity, ctrl_in_w, ctrl_in_w + PD * PCH, ctrl_in_b, p_ctrl,
                   PCH, 2 * PD, PD, 2 };
        tf32_gemm_multi<<<dim3(8, 16, 2), 256, GEMM_SMEM_BYTES>>>(dd, dc, dc);
    }

    // co = ctrl @ ctrl_out_w + ctrl_out_b
    {
        GDesc d { p_ctrl, nullptr, ctrl_out_w, nullptr, ctrl_out_b, p_co, 3 * PD, PCH, PCH, 0 };
        tf32_gemm_multi<<<dim3(24, 16, 1), 256, GEMM_SMEM_BYTES>>>(d, d, d);
    }

    // fused state update + rmsnorm(ln2)
    fuse1_rms_kernel<<<PN, 256>>>(p_co, velocity, p_o, out_mucur, hidden, ln2_w,
                                  out_vnext, p_hidmid, p_xnorm);

    router_kernel<<<(PN + 7) / 8, 256>>>(out_mucur, mu_router, token_ids);

    moe_gemm_kernel<<<dim3(32, 16, PE), 256, GEMM_SMEM_BYTES>>>(p_xnorm, w_gate, w_up,
                                               (size_t)PD * PF, p_G, p_U,
                                               nullptr, PF, PD, 16);
    midcombine_kernel<<<(PN * PF + 255) / 256, 256>>>();

    moe_gemm_kernel<<<dim3(8, 16, PE), 256, GEMM_SMEM_BYTES>>>(p_mid, w_down, nullptr,
                                              (size_t)PF * PD, out_hidden, nullptr,
                                              p_hidmid, PD, PF, 8);
}

// round 17
// speedup vs baseline: 1.3136x; 1.1449x over previous
#include <cuda_runtime.h>
#include <math.h>
#include <stdint.h>

// ---------------- problem constants ----------------
#define PN   2048
#define PD   1024
#define PH   16
#define PKV  4
#define PDH  64
#define PE   8
#define PF   2048
#define PCH  64
#define P_EPS 1e-6f
#define P_DT  0.1f
#define P_BASE_SCALE 10.0f

// GEMM k-tile and smem geometry (dynamic smem)
#define KT      32
#define ASTR    36
#define BSTR    136
#define ASZ     (128 * ASTR)
#define ASZ64   (64 * ASTR)
#define BSZ     (KT * BSTR)
#define GEMM_SMEM_BYTES   ((2 * ASZ   + 2 * BSZ) * 4)   // 71680 B
#define GEMM_SMEM_BYTES64 ((2 * ASZ64 + 2 * BSZ) * 4)   // 53248 B

// ---------------- scratch ----------------
__device__ float g_hnorm[PN * PD];
__device__ float g_q[PN * PH * PDH];
__device__ float g_k[PN * PKV * PDH];
__device__ float g_v[PN * PKV * PDH];
__device__ float g_attno[PN * PD];
__device__ float g_o[PN * PD];
__device__ float g_ctrl[PN * PCH];
__device__ float g_co[PN * 3 * PD];
__device__ float g_hidmid[PN * PD];
__device__ float g_xnorm[PN * PD];
__device__ float g_G[PN * PF];
__device__ float g_U[PN * PF];
__device__ float g_mid[PN * PF];
__device__ float g_cosT[PN * 32];
__device__ float g_sinT[PN * 32];
__device__ int   g_elist[PE * PN];
__device__ int   g_ecount[PE];

// ---------------- helpers ----------------
__device__ __forceinline__ float sigmoidf_(float x) { return 1.0f / (1.0f + expf(-x)); }
__device__ __forceinline__ float softplusf_(float x) {
    return fmaxf(x, 0.0f) + log1pf(expf(-fabsf(x)));
}
__device__ __forceinline__ uint32_t f2tf32(float f) {
    uint32_t r; asm("cvt.rna.tf32.f32 %0, %1;" : "=r"(r) : "f"(f)); return r;
}
__device__ __forceinline__ void mma_tf32(float* d, const uint32_t* a, const uint32_t* b) {
    asm volatile(
        "mma.sync.aligned.m16n8k8.row.col.f32.tf32.tf32.f32 "
        "{%0,%1,%2,%3}, {%4,%5,%6,%7}, {%8,%9}, {%0,%1,%2,%3};"
        : "+f"(d[0]), "+f"(d[1]), "+f"(d[2]), "+f"(d[3])
        : "r"(a[0]), "r"(a[1]), "r"(a[2]), "r"(a[3]), "r"(b[0]), "r"(b[1]));
}

__global__ void zero_counts_kernel() {
    int t = threadIdx.x;
    if (t < PE) g_ecount[t] = 0;
}

__global__ void rope_table_kernel(const int* __restrict__ positions) {
    __shared__ float sm_inv[32];
    if (threadIdx.x < 32) {
        double inv = pow(10000.0, -((double)(2 * threadIdx.x)) / 64.0);
        sm_inv[threadIdx.x] = (float)inv;
    }
    __syncthreads();
    int i = blockIdx.x * 256 + threadIdx.x;
    if (i >= PN * 32) return;
    int n = i >> 5, f = i & 31;
    float ang = (float)positions[n] * sm_inv[f];
    float s, c;
    sincosf(ang, &s, &c);
    g_cosT[i] = c;
    g_sinT[i] = s;
}

__global__ void rmsnorm_kernel(const float* __restrict__ x, const float* __restrict__ w,
                               float* __restrict__ out) {
    int row = blockIdx.x;
    int tid = threadIdx.x;
    __shared__ float red[256];
    const float* xr = x + (size_t)row * PD;
    float s = 0.0f;
    for (int d = tid; d < PD; d += 256) { float v = xr[d]; s += v * v; }
    red[tid] = s; __syncthreads();
    for (int off = 128; off > 0; off >>= 1) {
        if (tid < off) red[tid] += red[tid + off];
        __syncthreads();
    }
    float scale = rsqrtf(red[0] / (float)PD + P_EPS);
    float* orow = out + (size_t)row * PD;
    for (int d = tid; d < PD; d += 256) orow[d] = xr[d] * scale * w[d];
}

// ---------------- multi-descriptor TF32 GEMM, 128x128 tile ----------------
struct GDesc {
    const float* A; const float* A2;
    const float* B; const float* B2;
    const float* bias;
    float* C;
    int Nc; int K; int K1; int flags;    // flags bit1: SiLU
};

__global__ __launch_bounds__(256, 2)
void tf32_gemm_multi(GDesc d0, GDesc d1, GDesc d2) {
    extern __shared__ uint32_t sm[];
    uint32_t* Asm = sm;
    uint32_t* Bsm = sm + 2 * ASZ;
#define AS_(b, r, k) Asm[(b) * ASZ + (r) * ASTR + (k)]
#define BS_(b, r, n) Bsm[(b) * BSZ + (r) * BSTR + (n)]

    GDesc d = (blockIdx.z == 0) ? d0 : ((blockIdx.z == 1) ? d1 : d2);
    int m0 = blockIdx.y * 128;
    int n0 = blockIdx.x * 128;
    if (n0 >= d.Nc) return;

    int tid  = threadIdx.x;
    int lane = tid & 31;
    int w    = tid >> 5;
    int wm   = w >> 1;
    int wn   = w & 1;

    int a_r  = tid >> 2;
    int a_kq = (tid & 3) * 4;
    int b_k  = tid >> 5;
    int b_nq = (tid & 31) * 4;

    float4 aV[4], bV[4];
    float acc[2][8][4];
#pragma unroll
    for (int mf = 0; mf < 2; mf++)
#pragma unroll
        for (int nf = 0; nf < 8; nf++)
#pragma unroll
            for (int c = 0; c < 4; c++) acc[mf][nf][c] = 0.0f;

    auto loadA = [&](int k0) {
        const float* Ap = d.A; int lda = d.K1; int kk = k0;
        if (k0 >= d.K1) { Ap = d.A2; lda = d.K - d.K1; kk = k0 - d.K1; }
#pragma unroll
        for (int i = 0; i < 2; i++) {
            int pos = m0 + a_r + i * 64;
            const float* row = &Ap[(size_t)pos * lda + kk + a_kq];
            aV[i * 2 + 0] = *reinterpret_cast<const float4*>(row);
            aV[i * 2 + 1] = *reinterpret_cast<const float4*>(row + 16);
        }
    };
    auto loadB = [&](int k0) {
        const float* Bp = d.B; int kk = k0;
        if (k0 >= d.K1) { Bp = d.B2; kk = k0 - d.K1; }
        int col = n0 + b_nq;
#pragma unroll
        for (int i = 0; i < 4; i++) {
            if (col < d.Nc) {
                bV[i] = *reinterpret_cast<const float4*>(&Bp[(size_t)(kk + b_k + i * 8) * d.Nc + col]);
            } else {
                bV[i] = make_float4(0.f, 0.f, 0.f, 0.f);
            }
        }
    };
    auto stsTile = [&](int buf) {
#pragma unroll
        for (int i = 0; i < 2; i++) {
            int r = a_r + i * 64;
#pragma unroll
            for (int j = 0; j < 2; j++) {
                float4 av = aV[i * 2 + j];
                uint4 at = make_uint4(f2tf32(av.x), f2tf32(av.y), f2tf32(av.z), f2tf32(av.w));
                *reinterpret_cast<uint4*>(&AS_(buf, r, a_kq + j * 16)) = at;
            }
        }
#pragma unroll
        for (int i = 0; i < 4; i++) {
            uint4 bt = make_uint4(f2tf32(bV[i].x), f2tf32(bV[i].y),
                                  f2tf32(bV[i].z), f2tf32(bV[i].w));
            *reinterpret_cast<uint4*>(&BS_(buf, b_k + i * 8, b_nq)) = bt;
        }
    };

    loadA(0); loadB(0);
    stsTile(0);
    __syncthreads();

    int buf = 0;
    for (int k0 = KT; k0 <= d.K; k0 += KT) {
        bool nxt = (k0 < d.K);
        if (nxt) { loadA(k0); loadB(k0); }
#pragma unroll
        for (int s = 0; s < 4; s++) {
            uint32_t afr[2][4], bfr[8][2];
            int kk = s * 8 + (lane & 3);
#pragma unroll
            for (int mf = 0; mf < 2; mf++) {
                int rb = wm * 32 + mf * 16 + (lane >> 2);
                afr[mf][0] = AS_(buf, rb, kk);
                afr[mf][1] = AS_(buf, rb + 8, kk);
                afr[mf][2] = AS_(buf, rb, kk + 4);
                afr[mf][3] = AS_(buf, rb + 8, kk + 4);
            }
#pragma unroll
            for (int nf = 0; nf < 8; nf++) {
                int cb = wn * 64 + nf * 8 + (lane >> 2);
                bfr[nf][0] = BS_(buf, kk, cb);
                bfr[nf][1] = BS_(buf, kk + 4, cb);
            }
#pragma unroll
            for (int mf = 0; mf < 2; mf++)
#pragma unroll
                for (int nf = 0; nf < 8; nf++)
                    mma_tf32(acc[mf][nf], afr[mf], bfr[nf]);
        }
        if (nxt) stsTile(buf ^ 1);
        __syncthreads();
        buf ^= 1;
    }

#pragma unroll
    for (int mf = 0; mf < 2; mf++) {
#pragma unroll
        for (int r2 = 0; r2 < 2; r2++) {
            int crow = m0 + wm * 32 + mf * 16 + (lane >> 2) + r2 * 8;
#pragma unroll
            for (int nf = 0; nf < 8; nf++) {
#pragma unroll
                for (int c2 = 0; c2 < 2; c2++) {
                    int col = n0 + wn * 64 + nf * 8 + (lane & 3) * 2 + c2;
                    if (col >= d.Nc) continue;
                    size_t ci = (size_t)crow * d.Nc + col;
                    float val = acc[mf][nf][r2 * 2 + c2];
                    if (d.bias) val += d.bias[col];
                    if (d.flags & 2) val = val / (1.0f + expf(-val));
                    d.C[ci] = val;
                }
            }
        }
    }
}

// ---------------- multi-descriptor TF32 GEMM, 64x128 tile (wave-filling variant) ----------------
__global__ __launch_bounds__(256, 2)
void tf32_gemm_multi64(GDesc d0, GDesc d1, GDesc d2) {
    extern __shared__ uint32_t sm[];
    uint32_t* Asm = sm;
    uint32_t* Bsm = sm + 2 * ASZ64;
#define AS64_(b, r, k) Asm[(b) * ASZ64 + (r) * ASTR + (k)]
#define BS64_(b, r, n) Bsm[(b) * BSZ + (r) * BSTR + (n)]

    GDesc d = (blockIdx.z == 0) ? d0 : ((blockIdx.z == 1) ? d1 : d2);
    int m0 = blockIdx.y * 64;
    int n0 = blockIdx.x * 128;
    if (n0 >= d.Nc) return;

    int tid  = threadIdx.x;
    int lane = tid & 31;
    int w    = tid >> 5;
    int wm   = w >> 1;
    int wn   = w & 1;

    int a_r  = tid >> 2;
    int a_kq = (tid & 3) * 4;
    int b_k  = tid >> 5;
    int b_nq = (tid & 31) * 4;

    float4 aV[2], bV[4];
    float acc[8][4];
#pragma unroll
    for (int nf = 0; nf < 8; nf++)
#pragma unroll
        for (int c = 0; c < 4; c++) acc[nf][c] = 0.0f;

    auto loadA = [&](int k0) {
        const float* Ap = d.A; int lda = d.K1; int kk = k0;
        if (k0 >= d.K1) { Ap = d.A2; lda = d.K - d.K1; kk = k0 - d.K1; }
        int pos = m0 + a_r;
        const float* row = &Ap[(size_t)pos * lda + kk + a_kq];
        aV[0] = *reinterpret_cast<const float4*>(row);
        aV[1] = *reinterpret_cast<const float4*>(row + 16);
    };
    auto loadB = [&](int k0) {
        const float* Bp = d.B; int kk = k0;
        if (k0 >= d.K1) { Bp = d.B2; kk = k0 - d.K1; }
        int col = n0 + b_nq;
#pragma unroll
        for (int i = 0; i < 4; i++) {
            if (col < d.Nc) {
                bV[i] = *reinterpret_cast<const float4*>(&Bp[(size_t)(kk + b_k + i * 8) * d.Nc + col]);
            } else {
                bV[i] = make_float4(0.f, 0.f, 0.f, 0.f);
            }
        }
    };
    auto stsTile = [&](int buf) {
#pragma unroll
        for (int j = 0; j < 2; j++) {
            float4 av = aV[j];
            uint4 at = make_uint4(f2tf32(av.x), f2tf32(av.y), f2tf32(av.z), f2tf32(av.w));
            *reinterpret_cast<uint4*>(&AS64_(buf, a_r, a_kq + j * 16)) = at;
        }
#pragma unroll
        for (int i = 0; i < 4; i++) {
            uint4 bt = make_uint4(f2tf32(bV[i].x), f2tf32(bV[i].y),
                                  f2tf32(bV[i].z), f2tf32(bV[i].w));
            *reinterpret_cast<uint4*>(&BS64_(buf, b_k + i * 8, b_nq)) = bt;
        }
    };

    loadA(0); loadB(0);
    stsTile(0);
    __syncthreads();

    int buf = 0;
    for (int k0 = KT; k0 <= d.K; k0 += KT) {
        bool nxt = (k0 < d.K);
        if (nxt) { loadA(k0); loadB(k0); }
#pragma unroll
        for (int s = 0; s < 4; s++) {
            uint32_t afr[4], bfr[8][2];
            int kk = s * 8 + (lane & 3);
            int rb = wm * 16 + (lane >> 2);
            afr[0] = AS64_(buf, rb, kk);
            afr[1] = AS64_(buf, rb + 8, kk);
            afr[2] = AS64_(buf, rb, kk + 4);
            afr[3] = AS64_(buf, rb + 8, kk + 4);
#pragma unroll
            for (int nf = 0; nf < 8; nf++) {
                int cb = wn * 64 + nf * 8 + (lane >> 2);
                bfr[nf][0] = BS64_(buf, kk, cb);
                bfr[nf][1] = BS64_(buf, kk + 4, cb);
            }
#pragma unroll
            for (int nf = 0; nf < 8; nf++)
                mma_tf32(acc[nf], afr, bfr[nf]);
        }
        if (nxt) stsTile(buf ^ 1);
        __syncthreads();
        buf ^= 1;
    }

#pragma unroll
    for (int r2 = 0; r2 < 2; r2++) {
        int crow = m0 + wm * 16 + (lane >> 2) + r2 * 8;
#pragma unroll
        for (int nf = 0; nf < 8; nf++) {
#pragma unroll
            for (int c2 = 0; c2 < 2; c2++) {
                int col = n0 + wn * 64 + nf * 8 + (lane & 3) * 2 + c2;
                if (col >= d.Nc) continue;
                size_t ci = (size_t)crow * d.Nc + col;
                float val = acc[nf][r2 * 2 + c2];
                if (d.bias) val += d.bias[col];
                if (d.flags & 2) val = val / (1.0f + expf(-val));
                d.C[ci] = val;
            }
        }
    }
}

// ---------------- MoE GEMM 128x128: grid.z = expert, gate/up split along x ----------------
__global__ __launch_bounds__(256, 2)
void moe_gemm_kernel(const float* __restrict__ A,
                     const float* __restrict__ Bg, const float* __restrict__ Bu,
                     size_t bStride, float* __restrict__ Cg, float* __restrict__ Cu,
                     const float* __restrict__ residual,
                     int Nc, int K, int xPart) {
    extern __shared__ uint32_t sm[];
    uint32_t* Asm = sm;
    uint32_t* Bsm = sm + 2 * ASZ;

    int e = blockIdx.z;
    int cnt = g_ecount[e];
    int m0 = blockIdx.y * 128;
    if (m0 >= cnt) return;
    int part = blockIdx.x / xPart;
    int n0 = (blockIdx.x % xPart) * 128;
    const float* B = (part ? Bu : Bg) + (size_t)e * bStride;
    float* C = part ? Cu : Cg;
    const int* gather = g_elist + e * PN;

    int tid  = threadIdx.x;
    int lane = tid & 31;
    int w    = tid >> 5;
    int wm   = w >> 1;
    int wn   = w & 1;

    int a_r  = tid >> 2;
    int a_kq = (tid & 3) * 4;
    int b_k  = tid >> 5;
    int b_nq = (tid & 31) * 4;

    float4 aV[4], bV[4];
    float acc[2][8][4];
#pragma unroll
    for (int mf = 0; mf < 2; mf++)
#pragma unroll
        for (int nf = 0; nf < 8; nf++)
#pragma unroll
            for (int c = 0; c < 4; c++) acc[mf][nf][c] = 0.0f;

    auto loadA = [&](int k0) {
#pragma unroll
        for (int i = 0; i < 2; i++) {
            int pos = m0 + a_r + i * 64;
            if (pos < cnt) {
                int ar = gather[pos];
                const float* row = &A[(size_t)ar * K + k0 + a_kq];
                aV[i * 2 + 0] = *reinterpret_cast<const float4*>(row);
                aV[i * 2 + 1] = *reinterpret_cast<const float4*>(row + 16);
            } else {
                aV[i * 2 + 0] = make_float4(0.f, 0.f, 0.f, 0.f);
                aV[i * 2 + 1] = make_float4(0.f, 0.f, 0.f, 0.f);
            }
        }
    };
    auto loadB = [&](int k0) {
        int col = n0 + b_nq;
#pragma unroll
        for (int i = 0; i < 4; i++)
            bV[i] = *reinterpret_cast<const float4*>(&B[(size_t)(k0 + b_k + i * 8) * Nc + col]);
    };
    auto stsTile = [&](int buf) {
#pragma unroll
        for (int i = 0; i < 2; i++) {
            int r = a_r + i * 64;
#pragma unroll
            for (int j = 0; j < 2; j++) {
                float4 av = aV[i * 2 + j];
                uint4 at = make_uint4(f2tf32(av.x), f2tf32(av.y), f2tf32(av.z), f2tf32(av.w));
                *reinterpret_cast<uint4*>(&AS_(buf, r, a_kq + j * 16)) = at;
            }
        }
#pragma unroll
        for (int i = 0; i < 4; i++) {
            uint4 bt = make_uint4(f2tf32(bV[i].x), f2tf32(bV[i].y),
                                  f2tf32(bV[i].z), f2tf32(bV[i].w));
            *reinterpret_cast<uint4*>(&BS_(buf, b_k + i * 8, b_nq)) = bt;
        }
    };

    loadA(0); loadB(0);
    stsTile(0);
    __syncthreads();

    int buf = 0;
    for (int k0 = KT; k0 <= K; k0 += KT) {
        bool nxt = (k0 < K);
        if (nxt) { loadA(k0); loadB(k0); }
#pragma unroll
        for (int s = 0; s < 4; s++) {
            uint32_t afr[2][4], bfr[8][2];
            int kk = s * 8 + (lane & 3);
#pragma unroll
            for (int mf = 0; mf < 2; mf++) {
                int rb = wm * 32 + mf * 16 + (lane >> 2);
                afr[mf][0] = AS_(buf, rb, kk);
                afr[mf][1] = AS_(buf, rb + 8, kk);
                afr[mf][2] = AS_(buf, rb, kk + 4);
                afr[mf][3] = AS_(buf, rb + 8, kk + 4);
            }
#pragma unroll
            for (int nf = 0; nf < 8; nf++) {
                int cb = wn * 64 + nf * 8 + (lane >> 2);
                bfr[nf][0] = BS_(buf, kk, cb);
                bfr[nf][1] = BS_(buf, kk + 4, cb);
            }
#pragma unroll
            for (int mf = 0; mf < 2; mf++)
#pragma unroll
                for (int nf = 0; nf < 8; nf++)
                    mma_tf32(acc[mf][nf], afr[mf], bfr[nf]);
        }
        if (nxt) stsTile(buf ^ 1);
        __syncthreads();
        buf ^= 1;
    }

#pragma unroll
    for (int mf = 0; mf < 2; mf++) {
#pragma unroll
        for (int r2 = 0; r2 < 2; r2++) {
            int pos = m0 + wm * 32 + mf * 16 + (lane >> 2) + r2 * 8;
            if (pos >= cnt) continue;
            int crow = gather[pos];
#pragma unroll
            for (int nf = 0; nf < 8; nf++) {
#pragma unroll
                for (int c2 = 0; c2 < 2; c2++) {
                    int col = n0 + wn * 64 + nf * 8 + (lane & 3) * 2 + c2;
                    size_t ci = (size_t)crow * Nc + col;
                    float val = acc[mf][nf][r2 * 2 + c2];
                    if (residual) val += residual[ci];
                    C[ci] = val;
                }
            }
        }
    }
}

// ---------------- MoE GEMM 64x128 (wave-filling variant for stage 2) ----------------
__global__ __launch_bounds__(256, 2)
void moe_gemm_kernel64(const float* __restrict__ A,
                       const float* __restrict__ Bg,
                       size_t bStride, float* __restrict__ Cg,
                       const float* __restrict__ residual,
                       int Nc, int K) {
    extern __shared__ uint32_t sm[];
    uint32_t* Asm = sm;
    uint32_t* Bsm = sm + 2 * ASZ64;

    int e = blockIdx.z;
    int cnt = g_ecount[e];
    int m0 = blockIdx.y * 64;
    if (m0 >= cnt) return;
    int n0 = blockIdx.x * 128;
    const float* B = Bg + (size_t)e * bStride;
    const int* gather = g_elist + e * PN;

    int tid  = threadIdx.x;
    int lane = tid & 31;
    int w    = tid >> 5;
    int wm   = w >> 1;
    int wn   = w & 1;

    int a_r  = tid >> 2;
    int a_kq = (tid & 3) * 4;
    int b_k  = tid >> 5;
    int b_nq = (tid & 31) * 4;

    float4 aV[2], bV[4];
    float acc[8][4];
#pragma unroll
    for (int nf = 0; nf < 8; nf++)
#pragma unroll
        for (int c = 0; c < 4; c++) acc[nf][c] = 0.0f;

    auto loadA = [&](int k0) {
        int pos = m0 + a_r;
        if (pos < cnt) {
            int ar = gather[pos];
            const float* row = &A[(size_t)ar * K + k0 + a_kq];
            aV[0] = *reinterpret_cast<const float4*>(row);
            aV[1] = *reinterpret_cast<const float4*>(row + 16);
        } else {
            aV[0] = make_float4(0.f, 0.f, 0.f, 0.f);
            aV[1] = make_float4(0.f, 0.f, 0.f, 0.f);
        }
    };
    auto loadB = [&](int k0) {
        int col = n0 + b_nq;
#pragma unroll
        for (int i = 0; i < 4; i++)
            bV[i] = *reinterpret_cast<const float4*>(&B[(size_t)(k0 + b_k + i * 8) * Nc + col]);
    };
    auto stsTile = [&](int buf) {
#pragma unroll
        for (int j = 0; j < 2; j++) {
            float4 av = aV[j];
            uint4 at = make_uint4(f2tf32(av.x), f2tf32(av.y), f2tf32(av.z), f2tf32(av.w));
            *reinterpret_cast<uint4*>(&AS64_(buf, a_r, a_kq + j * 16)) = at;
        }
#pragma unroll
        for (int i = 0; i < 4; i++) {
            uint4 bt = make_uint4(f2tf32(bV[i].x), f2tf32(bV[i].y),
                                  f2tf32(bV[i].z), f2tf32(bV[i].w));
            *reinterpret_cast<uint4*>(&BS64_(buf, b_k + i * 8, b_nq)) = bt;
        }
    };

    loadA(0); loadB(0);
    stsTile(0);
    __syncthreads();

    int buf = 0;
    for (int k0 = KT; k0 <= K; k0 += KT) {
        bool nxt = (k0 < K);
        if (nxt) { loadA(k0); loadB(k0); }
#pragma unroll
        for (int s = 0; s < 4; s++) {
            uint32_t afr[4], bfr[8][2];
            int kk = s * 8 + (lane & 3);
            int rb = wm * 16 + (lane >> 2);
            afr[0] = AS64_(buf, rb, kk);
            afr[1] = AS64_(buf, rb + 8, kk);
            afr[2] = AS64_(buf, rb, kk + 4);
            afr[3] = AS64_(buf, rb + 8, kk + 4);
#pragma unroll
            for (int nf = 0; nf < 8; nf++) {
                int cb = wn * 64 + nf * 8 + (lane >> 2);
                bfr[nf][0] = BS64_(buf, kk, cb);
                bfr[nf][1] = BS64_(buf, kk + 4, cb);
            }
#pragma unroll
            for (int nf = 0; nf < 8; nf++)
                mma_tf32(acc[nf], afr, bfr[nf]);
        }
        if (nxt) stsTile(buf ^ 1);
        __syncthreads();
        buf ^= 1;
    }

#pragma unroll
    for (int r2 = 0; r2 < 2; r2++) {
        int pos = m0 + wm * 16 + (lane >> 2) + r2 * 8;
        if (pos >= cnt) continue;
        int crow = gather[pos];
#pragma unroll
        for (int nf = 0; nf < 8; nf++) {
#pragma unroll
            for (int c2 = 0; c2 < 2; c2++) {
                int col = n0 + wn * 64 + nf * 8 + (lane & 3) * 2 + c2;
                size_t ci = (size_t)crow * Nc + col;
                float val = acc[nf][r2 * 2 + c2];
                if (residual) val += residual[ci];
                Cg[ci] = val;
            }
        }
    }
}

// ---------------- per-head RMSNorm + RoPE ----------------
__global__ void qknorm_rope_kernel(float* __restrict__ x, const float* __restrict__ w,
                                   int heads, int nrows) {
    int row = blockIdx.x * 8 + (threadIdx.x >> 5);
    if (row >= nrows) return;
    int lane = threadIdx.x & 31;
    int n = row / heads;
    float* base = x + (size_t)row * PDH;
    float x1 = base[lane];
    float x2 = base[lane + 32];
    float s = x1 * x1 + x2 * x2;
#pragma unroll
    for (int off = 16; off > 0; off >>= 1) s += __shfl_xor_sync(0xffffffffu, s, off);
    float scale = rsqrtf(s / (float)PDH + P_EPS);
    x1 *= scale * w[lane];
    x2 *= scale * w[lane + 32];
    float c  = g_cosT[n * 32 + lane];
    float sn = g_sinT[n * 32 + lane];
    base[lane]      = x1 * c - x2 * sn;
    base[lane + 32] = x2 * c + x1 * sn;
}

// ---------------- tensor-core flash attention ----------------
__global__ __launch_bounds__(256, 2)
void attn_tc_kernel(const float* __restrict__ q, const float* __restrict__ k,
                    const float* __restrict__ v, float* __restrict__ o) {
    __shared__ uint32_t Ks[32][68];
    __shared__ uint32_t Vs[32][72];
    __shared__ uint32_t Ps[128][36];

    int qb = blockIdx.x, h = blockIdx.y;
    int kvh = h >> 2;
    int q0 = qb * 128;
    int tid = threadIdx.x;
    int lane = tid & 31;
    int w = tid >> 5;
    int lr = lane >> 2, lc = lane & 3;

    uint32_t qfr[8][4];
    {
        const float* qb_ = q + (size_t)(q0 + w * 16) * PD + h * PDH;
#pragma unroll
        for (int ks = 0; ks < 8; ks++) {
            int c = ks * 8 + lc;
            qfr[ks][0] = f2tf32(qb_[(size_t)lr * PD + c]);
            qfr[ks][1] = f2tf32(qb_[(size_t)(lr + 8) * PD + c]);
            qfr[ks][2] = f2tf32(qb_[(size_t)lr * PD + c + 4]);
            qfr[ks][3] = f2tf32(qb_[(size_t)(lr + 8) * PD + c + 4]);
        }
    }

    float accO[8][4];
#pragma unroll
    for (int nf = 0; nf < 8; nf++)
#pragma unroll
        for (int c = 0; c < 4; c++) accO[nf][c] = 0.0f;
    float m0 = -INFINITY, m1 = -INFINITY, l0 = 0.0f, l1 = 0.0f;
    const float scale = 0.125f;

    for (int t = 0; t < PN / 32; t++) {
#pragma unroll
        for (int it = 0; it < 2; it++) {
            int i = tid + it * 256;
            int kv = i >> 4, d4 = (i & 15) * 4;
            size_t gi = (size_t)(t * 32 + kv) * (PKV * PDH) + kvh * PDH + d4;
            float4 kf = *reinterpret_cast<const float4*>(&k[gi]);
            float4 vf = *reinterpret_cast<const float4*>(&v[gi]);
            uint4 kt = make_uint4(f2tf32(kf.x), f2tf32(kf.y), f2tf32(kf.z), f2tf32(kf.w));
            uint4 vt = make_uint4(f2tf32(vf.x), f2tf32(vf.y), f2tf32(vf.z), f2tf32(vf.w));
            *reinterpret_cast<uint4*>(&Ks[kv][d4]) = kt;
            *reinterpret_cast<uint4*>(&Vs[kv][d4]) = vt;
        }
        __syncthreads();

        float sacc[4][4];
#pragma unroll
        for (int nf = 0; nf < 4; nf++)
#pragma unroll
            for (int c = 0; c < 4; c++) sacc[nf][c] = 0.0f;
#pragma unroll
        for (int ks = 0; ks < 8; ks++) {
#pragma unroll
            for (int nf = 0; nf < 4; nf++) {
                uint32_t b[2];
                b[0] = Ks[nf * 8 + lr][ks * 8 + lc];
                b[1] = Ks[nf * 8 + lr][ks * 8 + lc + 4];
                mma_tf32(sacc[nf], qfr[ks], b);
            }
        }

        float mloc0 = -INFINITY, mloc1 = -INFINITY;
#pragma unroll
        for (int nf = 0; nf < 4; nf++) {
#pragma unroll
            for (int c = 0; c < 4; c++) sacc[nf][c] *= scale;
            mloc0 = fmaxf(mloc0, fmaxf(sacc[nf][0], sacc[nf][1]));
            mloc1 = fmaxf(mloc1, fmaxf(sacc[nf][2], sacc[nf][3]));
        }
        mloc0 = fmaxf(mloc0, __shfl_xor_sync(0xffffffffu, mloc0, 1));
        mloc0 = fmaxf(mloc0, __shfl_xor_sync(0xffffffffu, mloc0, 2));
        mloc1 = fmaxf(mloc1, __shfl_xor_sync(0xffffffffu, mloc1, 1));
        mloc1 = fmaxf(mloc1, __shfl_xor_sync(0xffffffffu, mloc1, 2));
        float mn0 = fmaxf(m0, mloc0), mn1 = fmaxf(m1, mloc1);
        float corr0 = __expf(m0 - mn0), corr1 = __expf(m1 - mn1);
        float ls0 = 0.0f, ls1 = 0.0f;
        int prow = w * 16 + lr;
#pragma unroll
        for (int nf = 0; nf < 4; nf++) {
            float p00 = __expf(sacc[nf][0] - mn0);
            float p01 = __expf(sacc[nf][1] - mn0);
            float p10 = __expf(sacc[nf][2] - mn1);
            float p11 = __expf(sacc[nf][3] - mn1);
            ls0 += p00 + p01;
            ls1 += p10 + p11;
            int col = nf * 8 + 2 * lc;
            *reinterpret_cast<uint2*>(&Ps[prow][col])     = make_uint2(f2tf32(p00), f2tf32(p01));
            *reinterpret_cast<uint2*>(&Ps[prow + 8][col]) = make_uint2(f2tf32(p10), f2tf32(p11));
        }
        ls0 += __shfl_xor_sync(0xffffffffu, ls0, 1);
        ls0 += __shfl_xor_sync(0xffffffffu, ls0, 2);
        ls1 += __shfl_xor_sync(0xffffffffu, ls1, 1);
        ls1 += __shfl_xor_sync(0xffffffffu, ls1, 2);
        l0 = l0 * corr0 + ls0;
        l1 = l1 * corr1 + ls1;
        m0 = mn0; m1 = mn1;
#pragma unroll
        for (int nf = 0; nf < 8; nf++) {
            accO[nf][0] *= corr0; accO[nf][1] *= corr0;
            accO[nf][2] *= corr1; accO[nf][3] *= corr1;
        }
        __syncthreads();

#pragma unroll
        for (int ks2 = 0; ks2 < 4; ks2++) {
            uint32_t a[4];
            a[0] = Ps[w * 16 + lr][ks2 * 8 + lc];
            a[1] = Ps[w * 16 + lr + 8][ks2 * 8 + lc];
            a[2] = Ps[w * 16 + lr][ks2 * 8 + lc + 4];
            a[3] = Ps[w * 16 + lr + 8][ks2 * 8 + lc + 4];
#pragma unroll
            for (int nf = 0; nf < 8; nf++) {
                uint32_t b[2];
                b[0] = Vs[ks2 * 8 + lc][nf * 8 + lr];
                b[1] = Vs[ks2 * 8 + lc + 4][nf * 8 + lr];
                mma_tf32(accO[nf], a, b);
            }
        }
        __syncthreads();
    }

    float il0 = 1.0f / l0, il1 = 1.0f / l1;
    int row0 = q0 + w * 16 + lr;
#pragma unroll
    for (int nf = 0; nf < 8; nf++) {
        int col = h * PDH + nf * 8 + 2 * lc;
        *reinterpret_cast<float2*>(&o[(size_t)row0 * PD + col]) =
            make_float2(accO[nf][0] * il0, accO[nf][1] * il0);
        *reinterpret_cast<float2*>(&o[(size_t)(row0 + 8) * PD + col]) =
            make_float2(accO[nf][2] * il1, accO[nf][3] * il1);
    }
}

// ---------------- fused state-update + rmsnorm(ln2): one block per row ----------------
__global__ void fuse1_rms_kernel(const float* __restrict__ co, const float* __restrict__ velocity,
                                 const float* __restrict__ o, const float* __restrict__ mu_cur,
                                 const float* __restrict__ hidden_in, const float* __restrict__ ln2_w,
                                 float* __restrict__ out_vnext, float* __restrict__ hidmid,
                                 float* __restrict__ xnorm) {
    int n = blockIdx.x;
    int tid = threadIdx.x;
    __shared__ float red[256];
    const float* cor = co + (size_t)n * 3 * PD;
    size_t rowo = (size_t)n * PD;

    float hv[4];
    float loc = 0.0f;
#pragma unroll
    for (int j = 0; j < 4; j++) {
        int d = tid + j * 256;
        float alpha = sigmoidf_(cor[d]);
        float beta  = fminf(softplusf_(cor[PD + d]), 2.0f);
        float gate  = sigmoidf_(cor[2 * PD + d]);
        float ov = o[rowo + d], mc = mu_cur[rowo + d], vel = velocity[rowo + d];
        float err = ov - mc;
        float vn = alpha * vel - beta * err;
        vn = fminf(fmaxf(vn, -10.0f), 10.0f);
        out_vnext[rowo + d] = vn;
        float h = hidden_in[rowo + d] + ov + P_DT * gate * vn;
        hv[j] = h;
        loc += h * h;
    }
    red[tid] = loc; __syncthreads();
    for (int off = 128; off > 0; off >>= 1) {
        if (tid < off) red[tid] += red[tid + off];
        __syncthreads();
    }
    float scale = rsqrtf(red[0] / (float)PD + P_EPS);
#pragma unroll
    for (int j = 0; j < 4; j++) {
        int d = tid + j * 256;
        hidmid[rowo + d] = hv[j];
        xnorm[rowo + d] = hv[j] * scale * ln2_w[d];
    }
}

// ---------------- router ----------------
__global__ void router_kernel(const float* __restrict__ mu_cur, const float* __restrict__ w,
                              const int* __restrict__ token_ids) {
    int tkn = blockIdx.x * 8 + (threadIdx.x >> 5);
    if (tkn >= PN) return;
    int lane = threadIdx.x & 31;
    float lg[PE];
#pragma unroll
    for (int e = 0; e < PE; e++) lg[e] = 0.0f;
    const float* xr = mu_cur + (size_t)tkn * PD;
    for (int d = lane; d < PD; d += 32) {
        float xv = xr[d];
        const float* wr = w + (size_t)d * PE;
#pragma unroll
        for (int e = 0; e < PE; e++) lg[e] += xv * wr[e];
    }
#pragma unroll
    for (int e = 0; e < PE; e++) {
#pragma unroll
        for (int off = 16; off > 0; off >>= 1)
            lg[e] += __shfl_xor_sync(0xffffffffu, lg[e], off);
    }
    if (lane == 0) {
        int b = token_ids[tkn] % PE;
        lg[b] += P_BASE_SCALE;
        int best = 0; float bv = lg[0];
#pragma unroll
        for (int e = 1; e < PE; e++) {
            if (lg[e] > bv) { bv = lg[e]; best = e; }
        }
        int slot = atomicAdd(&g_ecount[best], 1);
        g_elist[best * PN + slot] = tkn;
    }
}

__global__ void midcombine_kernel() {
    size_t i = (size_t)blockIdx.x * blockDim.x + threadIdx.x;
    if (i >= (size_t)PN * PF) return;
    float gv = g_G[i];
    g_mid[i] = (gv / (1.0f + expf(-gv))) * g_U[i];
}

// ---------------- host launch ----------------
static inline void* sym_addr(const void* sym) {
    void* p = nullptr;
    cudaGetSymbolAddress(&p, sym);
    return p;
}

extern "C" void kernel_launch(void* const* d_in, const int* in_sizes, int n_in,
                              void* d_out, int out_size) {
    const float* hidden    = (const float*)d_in[0];
    const int*   positions = (const int*)d_in[1];
    const float* velocity  = (const float*)d_in[2];
    const int*   token_ids = (const int*)d_in[3];
    const float* mu_prev   = (const float*)d_in[4];
    const float* ln1_w     = (const float*)d_in[5];
    const float* ln2_w     = (const float*)d_in[6];
    const float* wq        = (const float*)d_in[7];
    const float* wk        = (const float*)d_in[8];
    const float* wv        = (const float*)d_in[9];
    const float* wo        = (const float*)d_in[10];
    const float* w_mu_q    = (const float*)d_in[11];
    const float* w_mu_k    = (const float*)d_in[12];
    const float* w_mu_v    = (const float*)d_in[13];
    const float* qnorm_w   = (const float*)d_in[14];
    const float* knorm_w   = (const float*)d_in[15];
    const float* dyn_mu    = (const float*)d_in[16];
    const float* dyn_proj  = (const float*)d_in[17];
    const float* ctrl_in_w = (const float*)d_in[18];
    const float* ctrl_in_b = (const float*)d_in[19];
    const float* ctrl_out_w= (const float*)d_in[20];
    const float* ctrl_out_b= (const float*)d_in[21];
    const float* mu_router = (const float*)d_in[22];
    const float* w_gate    = (const float*)d_in[23];
    const float* w_up      = (const float*)d_in[24];
    const float* w_down    = (const float*)d_in[25];

    float* out_hidden = (float*)d_out;
    float* out_vnext  = out_hidden + (size_t)PN * PD;
    float* out_mucur  = out_vnext  + (size_t)PN * PD;

    float* p_hnorm  = (float*)sym_addr(g_hnorm);
    float* p_q      = (float*)sym_addr(g_q);
    float* p_k      = (float*)sym_addr(g_k);
    float* p_v      = (float*)sym_addr(g_v);
    float* p_attno  = (float*)sym_addr(g_attno);
    float* p_o      = (float*)sym_addr(g_o);
    float* p_ctrl   = (float*)sym_addr(g_ctrl);
    float* p_co     = (float*)sym_addr(g_co);
    float* p_hidmid = (float*)sym_addr(g_hidmid);
    float* p_xnorm  = (float*)sym_addr(g_xnorm);
    float* p_G      = (float*)sym_addr(g_G);
    float* p_U      = (float*)sym_addr(g_U);
    float* p_mid    = (float*)sym_addr(g_mid);

    // opt-in to >48KB dynamic smem (host-side attribute, not an allocation)
    static bool attr_done = false;
    if (!attr_done) {
        cudaFuncSetAttribute(tf32_gemm_multi,
                             cudaFuncAttributeMaxDynamicSharedMemorySize, GEMM_SMEM_BYTES);
        cudaFuncSetAttribute(tf32_gemm_multi64,
                             cudaFuncAttributeMaxDynamicSharedMemorySize, GEMM_SMEM_BYTES64);
        cudaFuncSetAttribute(moe_gemm_kernel,
                             cudaFuncAttributeMaxDynamicSharedMemorySize, GEMM_SMEM_BYTES);
        cudaFuncSetAttribute(moe_gemm_kernel64,
                             cudaFuncAttributeMaxDynamicSharedMemorySize, GEMM_SMEM_BYTES64);
        attr_done = true;
    }

    zero_counts_kernel<<<1, 32>>>();
    rope_table_kernel<<<(PN * 32 + 255) / 256, 256>>>(positions);
    rmsnorm_kernel<<<PN, 256>>>(hidden, ln1_w, p_hnorm);

    // QKV in ONE launch (128-tile; 192 active blocks)
    {
        GDesc dq { p_hnorm, mu_prev, wq, w_mu_q, nullptr, p_q, PH * PDH, 2 * PD, PD, 0 };
        GDesc dk { p_hnorm, mu_prev, wk, w_mu_k, nullptr, p_k, PKV * PDH, 2 * PD, PD, 0 };
        GDesc dv { p_hnorm, mu_prev, wv, w_mu_v, nullptr, p_v, PKV * PDH, 2 * PD, PD, 0 };
        tf32_gemm_multi<<<dim3(8, 16, 3), 256, GEMM_SMEM_BYTES>>>(dq, dk, dv);
    }

    qknorm_rope_kernel<<<(PN * PH + 7) / 8, 256>>>(p_q, qnorm_w, PH, PN * PH);
    qknorm_rope_kernel<<<(PN * PKV + 7) / 8, 256>>>(p_k, knorm_w, PKV, PN * PKV);

    attn_tc_kernel<<<dim3(PN / 128, PH), 256>>>(p_q, p_k, p_v, p_attno);

    // o = attno @ wo   (64-tile: 256 blocks)
    {
        GDesc d { p_attno, nullptr, wo, nullptr, nullptr, p_o, PD, PD, PD, 0 };
        tf32_gemm_multi64<<<dim3(8, 32, 1), 256, GEMM_SMEM_BYTES64>>>(d, d, d);
    }

    // dyn-proj and ctrl concurrently (64-tile: 288 active blocks)
    {
        GDesc dd { p_o, nullptr, dyn_proj, nullptr, dyn_mu, out_mucur, PD, PD, PD, 0 };
        GDesc dc { p_o, velocity, ctrl_in_w, ctrl_in_w + PD * PCH, ctrl_in_b, p_ctrl,
                   PCH, 2 * PD, PD, 2 };
        tf32_gemm_multi64<<<dim3(8, 32, 2), 256, GEMM_SMEM_BYTES64>>>(dd, dc, dc);
    }

    // co = ctrl @ ctrl_out_w + ctrl_out_b (128-tile: 384 blocks, tiny K)
    {
        GDesc d { p_ctrl, nullptr, ctrl_out_w, nullptr, ctrl_out_b, p_co, 3 * PD, PCH, PCH, 0 };
        tf32_gemm_multi<<<dim3(24, 16, 1), 256, GEMM_SMEM_BYTES>>>(d, d, d);
    }

    // fused state update + rmsnorm(ln2)
    fuse1_rms_kernel<<<PN, 256>>>(p_co, velocity, p_o, out_mucur, hidden, ln2_w,
                                  out_vnext, p_hidmid, p_xnorm);

    router_kernel<<<(PN + 7) / 8, 256>>>(out_mucur, mu_router, token_ids);

    // MoE stage 1 (128-tile: ~512 active blocks)
    moe_gemm_kernel<<<dim3(32, 16, PE), 256, GEMM_SMEM_BYTES>>>(p_xnorm, w_gate, w_up,
                                               (size_t)PD * PF, p_G, p_U,
                                               nullptr, PF, PD, 16);
    midcombine_kernel<<<(PN * PF + 255) / 256, 256>>>();

    // MoE stage 2 (64-tile: ~256 active blocks)
    moe_gemm_kernel64<<<dim3(8, 32, PE), 256, GEMM_SMEM_BYTES64>>>(
        p_mid, w_down, (size_t)PF * PD, out_hidden, p_hidmid, PD, PF);
}